// round 1
// baseline (speedup 1.0000x reference)
#include <cuda_runtime.h>
#include <cuda_bf16.h>
#include <math.h>

// Problem constants (hardcoded to the reference shapes)
#define BATCH 2
#define SEQ   2048
#define DMODEL 1024
#define NHEADS 16
#define DK    64            // DMODEL / NHEADS
#define MROWS (BATCH*SEQ)   // 4096

// ---------------------------------------------------------------------------
// Scratch (device globals; no allocation allowed)
// ---------------------------------------------------------------------------
__device__ float g_Q[MROWS * DMODEL];
__device__ float g_K[MROWS * DMODEL];
__device__ float g_V[MROWS * DMODEL];
__device__ float g_O[MROWS * DMODEL];

// ---------------------------------------------------------------------------
// SGEMM (NT):  C[m,n] = sum_k A[m,k] * B[n,k] + bias[n]
// A: [M,K] row-major, B: [N,K] row-major. M=4096, N=1024, K=1024 (all /64,/16)
// 64x64 tile, 256 threads (16x16), 4x4 microtile, TK=16
// ---------------------------------------------------------------------------
#define GT 64
#define GK 16

__global__ __launch_bounds__(256) void sgemm_nt_bias(
    const float* __restrict__ A, const float* __restrict__ B,
    const float* __restrict__ bias, float* __restrict__ C,
    int M, int N, int K)
{
    __shared__ float As[GT][GK + 1];
    __shared__ float Bs[GT][GK + 1];

    const int tx = threadIdx.x & 15;
    const int ty = threadIdx.x >> 4;
    const int t  = threadIdx.x;

    const int mbase = blockIdx.y * GT;
    const int nbase = blockIdx.x * GT;

    // loading map: thread t loads one float4: row = t/4, kq = t%4
    const int lr = t >> 2;
    const int lk = (t & 3) * 4;

    float acc[4][4];
#pragma unroll
    for (int i = 0; i < 4; i++)
#pragma unroll
        for (int j = 0; j < 4; j++) acc[i][j] = 0.f;

    for (int k0 = 0; k0 < K; k0 += GK) {
        // stage A tile
        {
            float4 va = *reinterpret_cast<const float4*>(&A[(size_t)(mbase + lr) * K + k0 + lk]);
            As[lr][lk + 0] = va.x; As[lr][lk + 1] = va.y;
            As[lr][lk + 2] = va.z; As[lr][lk + 3] = va.w;
            float4 vb = *reinterpret_cast<const float4*>(&B[(size_t)(nbase + lr) * K + k0 + lk]);
            Bs[lr][lk + 0] = vb.x; Bs[lr][lk + 1] = vb.y;
            Bs[lr][lk + 2] = vb.z; Bs[lr][lk + 3] = vb.w;
        }
        __syncthreads();

#pragma unroll
        for (int kk = 0; kk < GK; kk++) {
            float a[4], b[4];
#pragma unroll
            for (int i = 0; i < 4; i++) a[i] = As[ty * 4 + i][kk];
#pragma unroll
            for (int j = 0; j < 4; j++) b[j] = Bs[tx * 4 + j][kk];
#pragma unroll
            for (int i = 0; i < 4; i++)
#pragma unroll
                for (int j = 0; j < 4; j++) acc[i][j] = fmaf(a[i], b[j], acc[i][j]);
        }
        __syncthreads();
    }

#pragma unroll
    for (int i = 0; i < 4; i++) {
        int row = mbase + ty * 4 + i;
#pragma unroll
        for (int j = 0; j < 4; j++) {
            int col = nbase + tx * 4 + j;
            C[(size_t)row * N + col] = acc[i][j] + bias[col];
        }
    }
}

// ---------------------------------------------------------------------------
// Flash attention, fp32. grid = (SEQ/64, NHEADS, BATCH), block = 256 (16x16)
// Each CTA: 64 queries of one (b,h); loops over 32 KV tiles of 64.
// smem (dynamic): Qs,Ks,Vs,Ps each [64][65] floats = 66560 B
// ---------------------------------------------------------------------------
#define AP 65   // padded row stride

__global__ __launch_bounds__(256) void attn_kernel(
    const float* __restrict__ Q, const float* __restrict__ K,
    const float* __restrict__ V, float* __restrict__ O)
{
    extern __shared__ float sh[];
    float* Qs = sh;                 // [64][AP]
    float* Ks = Qs + 64 * AP;
    float* Vs = Ks + 64 * AP;
    float* Ps = Vs + 64 * AP;

    const int tx = threadIdx.x & 15;
    const int ty = threadIdx.x >> 4;
    const int t  = threadIdx.x;

    const int qbase = blockIdx.x * 64;
    const int h     = blockIdx.y;
    const int b     = blockIdx.z;
    const int hbase = h * DK;

    // global row base for this (b, s)
    const size_t gq = ((size_t)b * SEQ + qbase) * DMODEL + hbase;

    // load Q tile: 64 rows x 64 cols -> 16 floats/thread (4x float4)
    {
        const int lr = t >> 2;          // 0..63
        const int lk = (t & 3) * 16;    // 0,16,32,48
#pragma unroll
        for (int q4 = 0; q4 < 4; q4++) {
            float4 v4 = *reinterpret_cast<const float4*>(&Q[gq + (size_t)lr * DMODEL + lk + q4 * 4]);
            Qs[lr * AP + lk + q4 * 4 + 0] = v4.x;
            Qs[lr * AP + lk + q4 * 4 + 1] = v4.y;
            Qs[lr * AP + lk + q4 * 4 + 2] = v4.z;
            Qs[lr * AP + lk + q4 * 4 + 3] = v4.w;
        }
    }

    float m_i[4], l_i[4], o[4][4];
#pragma unroll
    for (int i = 0; i < 4; i++) {
        m_i[i] = -1e30f; l_i[i] = 0.f;
#pragma unroll
        for (int j = 0; j < 4; j++) o[i][j] = 0.f;
    }

    const float scale = 0.125f;  // 1/sqrt(64)

    for (int j0 = 0; j0 < SEQ; j0 += 64) {
        // stage K and V tiles
        const size_t gk = ((size_t)b * SEQ + j0) * DMODEL + hbase;
        {
            const int lr = t >> 2;
            const int lk = (t & 3) * 16;
#pragma unroll
            for (int q4 = 0; q4 < 4; q4++) {
                float4 vk = *reinterpret_cast<const float4*>(&K[gk + (size_t)lr * DMODEL + lk + q4 * 4]);
                Ks[lr * AP + lk + q4 * 4 + 0] = vk.x;
                Ks[lr * AP + lk + q4 * 4 + 1] = vk.y;
                Ks[lr * AP + lk + q4 * 4 + 2] = vk.z;
                Ks[lr * AP + lk + q4 * 4 + 3] = vk.w;
                float4 vv = *reinterpret_cast<const float4*>(&V[gk + (size_t)lr * DMODEL + lk + q4 * 4]);
                Vs[lr * AP + lk + q4 * 4 + 0] = vv.x;
                Vs[lr * AP + lk + q4 * 4 + 1] = vv.y;
                Vs[lr * AP + lk + q4 * 4 + 2] = vv.z;
                Vs[lr * AP + lk + q4 * 4 + 3] = vv.w;
            }
        }
        __syncthreads();

        // scores S = Q K^T  (per-thread 4x4)
        float s[4][4];
#pragma unroll
        for (int i = 0; i < 4; i++)
#pragma unroll
            for (int j = 0; j < 4; j++) s[i][j] = 0.f;

#pragma unroll 8
        for (int kk = 0; kk < DK; kk++) {
            float a[4], bb[4];
#pragma unroll
            for (int i = 0; i < 4; i++) a[i] = Qs[(ty * 4 + i) * AP + kk];
#pragma unroll
            for (int j = 0; j < 4; j++) bb[j] = Ks[(tx * 4 + j) * AP + kk];
#pragma unroll
            for (int i = 0; i < 4; i++)
#pragma unroll
                for (int j = 0; j < 4; j++) s[i][j] = fmaf(a[i], bb[j], s[i][j]);
        }

        // online softmax (rows owned by ty-groups = 16 lanes in one half-warp)
        float alpha[4];
#pragma unroll
        for (int i = 0; i < 4; i++) {
            float mx = -1e30f;
#pragma unroll
            for (int j = 0; j < 4; j++) {
                s[i][j] *= scale;
                mx = fmaxf(mx, s[i][j]);
            }
#pragma unroll
            for (int off = 8; off >= 1; off >>= 1)
                mx = fmaxf(mx, __shfl_xor_sync(0xffffffffu, mx, off));
            float m_new = fmaxf(m_i[i], mx);
            alpha[i] = __expf(m_i[i] - m_new);
            m_i[i] = m_new;

            float rs = 0.f;
#pragma unroll
            for (int j = 0; j < 4; j++) {
                float p = __expf(s[i][j] - m_new);
                s[i][j] = p;                 // reuse s as P
                rs += p;
            }
#pragma unroll
            for (int off = 8; off >= 1; off >>= 1)
                rs += __shfl_xor_sync(0xffffffffu, rs, off);
            l_i[i] = l_i[i] * alpha[i] + rs;
#pragma unroll
            for (int j = 0; j < 4; j++) o[i][j] *= alpha[i];
        }

        // publish P to smem
#pragma unroll
        for (int i = 0; i < 4; i++)
#pragma unroll
            for (int j = 0; j < 4; j++)
                Ps[(ty * 4 + i) * AP + tx * 4 + j] = s[i][j];
        __syncthreads();

        // O += P @ V
#pragma unroll 8
        for (int c = 0; c < 64; c++) {
            float p[4], vv[4];
#pragma unroll
            for (int i = 0; i < 4; i++) p[i] = Ps[(ty * 4 + i) * AP + c];
#pragma unroll
            for (int j = 0; j < 4; j++) vv[j] = Vs[c * AP + tx * 4 + j];
#pragma unroll
            for (int i = 0; i < 4; i++)
#pragma unroll
                for (int j = 0; j < 4; j++) o[i][j] = fmaf(p[i], vv[j], o[i][j]);
        }
        __syncthreads();
    }

    // finalize and store: O[b, qbase+r, hbase+d]
#pragma unroll
    for (int i = 0; i < 4; i++) {
        float inv_l = 1.f / l_i[i];
        size_t row = (size_t)b * SEQ + qbase + ty * 4 + i;
#pragma unroll
        for (int j = 0; j < 4; j++)
            O[row * DMODEL + hbase + tx * 4 + j] = o[i][j] * inv_l;
    }
}

// ---------------------------------------------------------------------------
// launch
// ---------------------------------------------------------------------------
extern "C" void kernel_launch(void* const* d_in, const int* in_sizes, int n_in,
                              void* d_out, int out_size)
{
    const float* q   = (const float*)d_in[0];
    const float* k   = (const float*)d_in[1];
    const float* v   = (const float*)d_in[2];
    const float* W_q = (const float*)d_in[3];
    const float* b_q = (const float*)d_in[4];
    const float* W_k = (const float*)d_in[5];
    const float* b_k = (const float*)d_in[6];
    const float* W_v = (const float*)d_in[7];
    const float* b_v = (const float*)d_in[8];
    const float* W_o = (const float*)d_in[9];
    const float* b_o = (const float*)d_in[10];
    float* out = (float*)d_out;

    float *Qp, *Kp, *Vp, *Op;
    cudaGetSymbolAddress((void**)&Qp, g_Q);
    cudaGetSymbolAddress((void**)&Kp, g_K);
    cudaGetSymbolAddress((void**)&Vp, g_V);
    cudaGetSymbolAddress((void**)&Op, g_O);

    dim3 gblk(256);
    dim3 ggrid(DMODEL / GT, MROWS / GT);   // (16, 64)

    sgemm_nt_bias<<<ggrid, gblk>>>(q, W_q, b_q, Qp, MROWS, DMODEL, DMODEL);
    sgemm_nt_bias<<<ggrid, gblk>>>(k, W_k, b_k, Kp, MROWS, DMODEL, DMODEL);
    sgemm_nt_bias<<<ggrid, gblk>>>(v, W_v, b_v, Vp, MROWS, DMODEL, DMODEL);

    static int attr_set = 0;
    size_t shmem = 4 * 64 * AP * sizeof(float);  // 66560 B
    cudaFuncSetAttribute(attn_kernel, cudaFuncAttributeMaxDynamicSharedMemorySize, (int)shmem);

    dim3 agrid(SEQ / 64, NHEADS, BATCH);   // (32, 16, 2)
    attn_kernel<<<agrid, dim3(256), shmem>>>(Qp, Kp, Vp, Op);

    sgemm_nt_bias<<<ggrid, gblk>>>(Op, W_o, b_o, out, MROWS, DMODEL, DMODEL);
    (void)attr_set; (void)in_sizes; (void)n_in; (void)out_size;
}

// round 3
// speedup vs baseline: 1.4926x; 1.4926x over previous
#include <cuda_runtime.h>
#include <cuda_bf16.h>
#include <cstdint>
#include <math.h>

// Problem constants
#define BATCH 2
#define SEQ   2048
#define DMODEL 1024
#define NHEADS 16
#define DK    64
#define MROWS (BATCH*SEQ)   // 4096

// ---------------------------------------------------------------------------
// Scratch
// ---------------------------------------------------------------------------
__device__ float g_Q[MROWS * DMODEL];
__device__ float g_K[MROWS * DMODEL];
__device__ float g_V[MROWS * DMODEL];
__device__ float g_O[MROWS * DMODEL];

__device__ __forceinline__ uint32_t tf32_rn(float x) {
    uint32_t y; asm("cvt.rna.tf32.f32 %0, %1;" : "=r"(y) : "f"(x));
    return y;
}

// ---------------------------------------------------------------------------
// TF32 mma.sync GEMM (NT): C[m,n] = sum_k A[m,k]*B[n,k] + bias[n]
// A: [M,K] rm, B: [N,K] rm. CTA tile 128x128, 8 warps of 64x32, K-chunk 16.
// Double-buffered smem + register prefetch. mma.m16n8k8.tf32.
// ---------------------------------------------------------------------------
#define BM 128
#define BN 128
#define BKC 16
#define ASTR 20   // smem row stride (floats): conflict-free + float4-alignable

__global__ __launch_bounds__(256) void gemm_tf32mma(
    const float* __restrict__ A, const float* __restrict__ B,
    const float* __restrict__ bias, float* __restrict__ C,
    int M, int N, int K)
{
    __shared__ uint32_t As[2][BM * ASTR];
    __shared__ uint32_t Bs[2][BN * ASTR];

    const int t    = threadIdx.x;
    const int wid  = t >> 5;
    const int lane = t & 31;
    const int mbase = blockIdx.y * BM;
    const int nbase = blockIdx.x * BN;

    // global load map: thread t -> row t/2, 8-float segment (t&1)*8
    const int lrow = t >> 1;
    const int lseg = (t & 1) * 8;
    const float* Ap = A + (size_t)(mbase + lrow) * K + lseg;
    const float* Bp = B + (size_t)(nbase + lrow) * K + lseg;
    const int sidx = lrow * ASTR + lseg;

    // warp tile: wm = wid&1 (row 0/64), wn = wid>>1 (col 0..3 * 32)
    const int rm = (wid & 1) * 64;
    const int cn = (wid >> 1) * 32;
    const int lq = lane >> 2;   // 0..7
    const int lr4 = lane & 3;   // 0..3

    float acc[4][4][4];
#pragma unroll
    for (int mt = 0; mt < 4; mt++)
#pragma unroll
        for (int nt = 0; nt < 4; nt++)
#pragma unroll
            for (int i = 0; i < 4; i++) acc[mt][nt][i] = 0.f;

    const int NCH = K / BKC;   // 64

    // prologue: load chunk 0
    {
        float4 a0 = *reinterpret_cast<const float4*>(Ap);
        float4 a1 = *reinterpret_cast<const float4*>(Ap + 4);
        float4 b0 = *reinterpret_cast<const float4*>(Bp);
        float4 b1 = *reinterpret_cast<const float4*>(Bp + 4);
        uint32_t* sa = &As[0][sidx];
        sa[0] = tf32_rn(a0.x); sa[1] = tf32_rn(a0.y); sa[2] = tf32_rn(a0.z); sa[3] = tf32_rn(a0.w);
        sa[4] = tf32_rn(a1.x); sa[5] = tf32_rn(a1.y); sa[6] = tf32_rn(a1.z); sa[7] = tf32_rn(a1.w);
        uint32_t* sb = &Bs[0][sidx];
        sb[0] = tf32_rn(b0.x); sb[1] = tf32_rn(b0.y); sb[2] = tf32_rn(b0.z); sb[3] = tf32_rn(b0.w);
        sb[4] = tf32_rn(b1.x); sb[5] = tf32_rn(b1.y); sb[6] = tf32_rn(b1.z); sb[7] = tf32_rn(b1.w);
    }
    __syncthreads();

    for (int c = 0; c < NCH; c++) {
        const int buf = c & 1;
        float4 pa0, pa1, pb0, pb1;
        if (c + 1 < NCH) {
            const float* ap = Ap + (c + 1) * BKC;
            const float* bp = Bp + (c + 1) * BKC;
            pa0 = *reinterpret_cast<const float4*>(ap);
            pa1 = *reinterpret_cast<const float4*>(ap + 4);
            pb0 = *reinterpret_cast<const float4*>(bp);
            pb1 = *reinterpret_cast<const float4*>(bp + 4);
        }

        const uint32_t* sA = As[buf];
        const uint32_t* sB = Bs[buf];
#pragma unroll
        for (int ks = 0; ks < 2; ks++) {
            const int k0 = ks * 8;
            uint32_t af[4][4], bf[4][2];
#pragma unroll
            for (int mt = 0; mt < 4; mt++) {
                const int r0 = rm + mt * 16;
                af[mt][0] = sA[(r0 + lq) * ASTR + k0 + lr4];
                af[mt][1] = sA[(r0 + 8 + lq) * ASTR + k0 + lr4];
                af[mt][2] = sA[(r0 + lq) * ASTR + k0 + 4 + lr4];
                af[mt][3] = sA[(r0 + 8 + lq) * ASTR + k0 + 4 + lr4];
            }
#pragma unroll
            for (int nt = 0; nt < 4; nt++) {
                const int c0 = cn + nt * 8;
                bf[nt][0] = sB[(c0 + lq) * ASTR + k0 + lr4];
                bf[nt][1] = sB[(c0 + lq) * ASTR + k0 + 4 + lr4];
            }
#pragma unroll
            for (int mt = 0; mt < 4; mt++)
#pragma unroll
                for (int nt = 0; nt < 4; nt++) {
                    float* d = acc[mt][nt];
                    asm volatile(
                        "mma.sync.aligned.m16n8k8.row.col.f32.tf32.tf32.f32 "
                        "{%0,%1,%2,%3}, {%4,%5,%6,%7}, {%8,%9}, {%0,%1,%2,%3};"
                        : "+f"(d[0]), "+f"(d[1]), "+f"(d[2]), "+f"(d[3])
                        : "r"(af[mt][0]), "r"(af[mt][1]), "r"(af[mt][2]), "r"(af[mt][3]),
                          "r"(bf[nt][0]), "r"(bf[nt][1]));
                }
        }

        if (c + 1 < NCH) {
            uint32_t* sa = &As[buf ^ 1][sidx];
            sa[0] = tf32_rn(pa0.x); sa[1] = tf32_rn(pa0.y); sa[2] = tf32_rn(pa0.z); sa[3] = tf32_rn(pa0.w);
            sa[4] = tf32_rn(pa1.x); sa[5] = tf32_rn(pa1.y); sa[6] = tf32_rn(pa1.z); sa[7] = tf32_rn(pa1.w);
            uint32_t* sb = &Bs[buf ^ 1][sidx];
            sb[0] = tf32_rn(pb0.x); sb[1] = tf32_rn(pb0.y); sb[2] = tf32_rn(pb0.z); sb[3] = tf32_rn(pb0.w);
            sb[4] = tf32_rn(pb1.x); sb[5] = tf32_rn(pb1.y); sb[6] = tf32_rn(pb1.z); sb[7] = tf32_rn(pb1.w);
            __syncthreads();
        }
    }

    // epilogue: write acc + bias.  c0:(row=lq, col=lr4*2) c1:col+1 c2:row+8 c3:row+8,col+1
#pragma unroll
    for (int mt = 0; mt < 4; mt++) {
        const int r0 = mbase + rm + mt * 16 + lq;
#pragma unroll
        for (int nt = 0; nt < 4; nt++) {
            const int col = nbase + cn + nt * 8 + lr4 * 2;
            const float bz0 = bias[col], bz1 = bias[col + 1];
            float2 v0 = make_float2(acc[mt][nt][0] + bz0, acc[mt][nt][1] + bz1);
            float2 v1 = make_float2(acc[mt][nt][2] + bz0, acc[mt][nt][3] + bz1);
            *reinterpret_cast<float2*>(&C[(size_t)r0 * N + col]) = v0;
            *reinterpret_cast<float2*>(&C[(size_t)(r0 + 8) * N + col]) = v1;
        }
    }
}

// ---------------------------------------------------------------------------
// Flash attention, fp32 (unchanged). grid=(32,16,2), block=256
// ---------------------------------------------------------------------------
#define AP 65

__global__ __launch_bounds__(256) void attn_kernel(
    const float* __restrict__ Q, const float* __restrict__ K,
    const float* __restrict__ V, float* __restrict__ O)
{
    extern __shared__ float sh[];
    float* Qs = sh;
    float* Ks = Qs + 64 * AP;
    float* Vs = Ks + 64 * AP;
    float* Ps = Vs + 64 * AP;

    const int tx = threadIdx.x & 15;
    const int ty = threadIdx.x >> 4;
    const int t  = threadIdx.x;

    const int qbase = blockIdx.x * 64;
    const int h     = blockIdx.y;
    const int b     = blockIdx.z;
    const int hbase = h * DK;

    const size_t gq = ((size_t)b * SEQ + qbase) * DMODEL + hbase;

    {
        const int lr = t >> 2;
        const int lk = (t & 3) * 16;
#pragma unroll
        for (int q4 = 0; q4 < 4; q4++) {
            float4 v4 = *reinterpret_cast<const float4*>(&Q[gq + (size_t)lr * DMODEL + lk + q4 * 4]);
            Qs[lr * AP + lk + q4 * 4 + 0] = v4.x;
            Qs[lr * AP + lk + q4 * 4 + 1] = v4.y;
            Qs[lr * AP + lk + q4 * 4 + 2] = v4.z;
            Qs[lr * AP + lk + q4 * 4 + 3] = v4.w;
        }
    }

    float m_i[4], l_i[4], o[4][4];
#pragma unroll
    for (int i = 0; i < 4; i++) {
        m_i[i] = -1e30f; l_i[i] = 0.f;
#pragma unroll
        for (int j = 0; j < 4; j++) o[i][j] = 0.f;
    }

    const float scale = 0.125f;

    for (int j0 = 0; j0 < SEQ; j0 += 64) {
        const size_t gk = ((size_t)b * SEQ + j0) * DMODEL + hbase;
        {
            const int lr = t >> 2;
            const int lk = (t & 3) * 16;
#pragma unroll
            for (int q4 = 0; q4 < 4; q4++) {
                float4 vk = *reinterpret_cast<const float4*>(&K[gk + (size_t)lr * DMODEL + lk + q4 * 4]);
                Ks[lr * AP + lk + q4 * 4 + 0] = vk.x;
                Ks[lr * AP + lk + q4 * 4 + 1] = vk.y;
                Ks[lr * AP + lk + q4 * 4 + 2] = vk.z;
                Ks[lr * AP + lk + q4 * 4 + 3] = vk.w;
                float4 vv = *reinterpret_cast<const float4*>(&V[gk + (size_t)lr * DMODEL + lk + q4 * 4]);
                Vs[lr * AP + lk + q4 * 4 + 0] = vv.x;
                Vs[lr * AP + lk + q4 * 4 + 1] = vv.y;
                Vs[lr * AP + lk + q4 * 4 + 2] = vv.z;
                Vs[lr * AP + lk + q4 * 4 + 3] = vv.w;
            }
        }
        __syncthreads();

        float s[4][4];
#pragma unroll
        for (int i = 0; i < 4; i++)
#pragma unroll
            for (int j = 0; j < 4; j++) s[i][j] = 0.f;

#pragma unroll 8
        for (int kk = 0; kk < DK; kk++) {
            float a[4], bb[4];
#pragma unroll
            for (int i = 0; i < 4; i++) a[i] = Qs[(ty * 4 + i) * AP + kk];
#pragma unroll
            for (int j = 0; j < 4; j++) bb[j] = Ks[(tx * 4 + j) * AP + kk];
#pragma unroll
            for (int i = 0; i < 4; i++)
#pragma unroll
                for (int j = 0; j < 4; j++) s[i][j] = fmaf(a[i], bb[j], s[i][j]);
        }

        float alpha[4];
#pragma unroll
        for (int i = 0; i < 4; i++) {
            float mx = -1e30f;
#pragma unroll
            for (int j = 0; j < 4; j++) {
                s[i][j] *= scale;
                mx = fmaxf(mx, s[i][j]);
            }
#pragma unroll
            for (int off = 8; off >= 1; off >>= 1)
                mx = fmaxf(mx, __shfl_xor_sync(0xffffffffu, mx, off));
            float m_new = fmaxf(m_i[i], mx);
            alpha[i] = __expf(m_i[i] - m_new);
            m_i[i] = m_new;

            float rs = 0.f;
#pragma unroll
            for (int j = 0; j < 4; j++) {
                float p = __expf(s[i][j] - m_new);
                s[i][j] = p;
                rs += p;
            }
#pragma unroll
            for (int off = 8; off >= 1; off >>= 1)
                rs += __shfl_xor_sync(0xffffffffu, rs, off);
            l_i[i] = l_i[i] * alpha[i] + rs;
#pragma unroll
            for (int j = 0; j < 4; j++) o[i][j] *= alpha[i];
        }

#pragma unroll
        for (int i = 0; i < 4; i++)
#pragma unroll
            for (int j = 0; j < 4; j++)
                Ps[(ty * 4 + i) * AP + tx * 4 + j] = s[i][j];
        __syncthreads();

#pragma unroll 8
        for (int c = 0; c < 64; c++) {
            float p[4], vv[4];
#pragma unroll
            for (int i = 0; i < 4; i++) p[i] = Ps[(ty * 4 + i) * AP + c];
#pragma unroll
            for (int j = 0; j < 4; j++) vv[j] = Vs[c * AP + tx * 4 + j];
#pragma unroll
            for (int i = 0; i < 4; i++)
#pragma unroll
                for (int j = 0; j < 4; j++) o[i][j] = fmaf(p[i], vv[j], o[i][j]);
        }
        __syncthreads();
    }

#pragma unroll
    for (int i = 0; i < 4; i++) {
        float inv_l = 1.f / l_i[i];
        size_t row = (size_t)b * SEQ + qbase + ty * 4 + i;
#pragma unroll
        for (int j = 0; j < 4; j++)
            O[row * DMODEL + hbase + tx * 4 + j] = o[i][j] * inv_l;
    }
}

// ---------------------------------------------------------------------------
// launch
// ---------------------------------------------------------------------------
extern "C" void kernel_launch(void* const* d_in, const int* in_sizes, int n_in,
                              void* d_out, int out_size)
{
    const float* q   = (const float*)d_in[0];
    const float* k   = (const float*)d_in[1];
    const float* v   = (const float*)d_in[2];
    const float* W_q = (const float*)d_in[3];
    const float* b_q = (const float*)d_in[4];
    const float* W_k = (const float*)d_in[5];
    const float* b_k = (const float*)d_in[6];
    const float* W_v = (const float*)d_in[7];
    const float* b_v = (const float*)d_in[8];
    const float* W_o = (const float*)d_in[9];
    const float* b_o = (const float*)d_in[10];
    float* out = (float*)d_out;

    float *Qp, *Kp, *Vp, *Op;
    cudaGetSymbolAddress((void**)&Qp, g_Q);
    cudaGetSymbolAddress((void**)&Kp, g_K);
    cudaGetSymbolAddress((void**)&Vp, g_V);
    cudaGetSymbolAddress((void**)&Op, g_O);

    dim3 ggrid(DMODEL / BN, MROWS / BM);   // (8, 32)

    gemm_tf32mma<<<ggrid, 256>>>(q, W_q, b_q, Qp, MROWS, DMODEL, DMODEL);
    gemm_tf32mma<<<ggrid, 256>>>(k, W_k, b_k, Kp, MROWS, DMODEL, DMODEL);
    gemm_tf32mma<<<ggrid, 256>>>(v, W_v, b_v, Vp, MROWS, DMODEL, DMODEL);

    const size_t ashm = 4 * 64 * AP * sizeof(float);  // 66560
    cudaFuncSetAttribute(attn_kernel, cudaFuncAttributeMaxDynamicSharedMemorySize, (int)ashm);
    dim3 agrid(SEQ / 64, NHEADS, BATCH);
    attn_kernel<<<agrid, dim3(256), ashm>>>(Qp, Kp, Vp, Op);

    gemm_tf32mma<<<ggrid, 256>>>(Op, W_o, b_o, out, MROWS, DMODEL, DMODEL);
    (void)in_sizes; (void)n_in; (void)out_size;
}

// round 4
// speedup vs baseline: 2.8707x; 1.9233x over previous
#include <cuda_runtime.h>
#include <cuda_bf16.h>
#include <cstdint>
#include <math.h>

// Problem constants
#define BATCH 2
#define SEQ   2048
#define DMODEL 1024
#define NHEADS 16
#define DK    64
#define MROWS (BATCH*SEQ)   // 4096

// ---------------------------------------------------------------------------
// Scratch
// ---------------------------------------------------------------------------
__device__ float g_Q[MROWS * DMODEL];
__device__ float g_K[MROWS * DMODEL];
__device__ float g_V[MROWS * DMODEL];
__device__ float g_O[MROWS * DMODEL];

__device__ __forceinline__ uint32_t tf32_rn(float x) {
    uint32_t y; asm("cvt.rna.tf32.f32 %0, %1;" : "=r"(y) : "f"(x));
    return y;
}

#define MMA_TF32(d, a0,a1,a2,a3, b0,b1) \
    asm volatile( \
        "mma.sync.aligned.m16n8k8.row.col.f32.tf32.tf32.f32 " \
        "{%0,%1,%2,%3}, {%4,%5,%6,%7}, {%8,%9}, {%0,%1,%2,%3};" \
        : "+f"((d)[0]), "+f"((d)[1]), "+f"((d)[2]), "+f"((d)[3]) \
        : "r"(a0), "r"(a1), "r"(a2), "r"(a3), "r"(b0), "r"(b1))

// ---------------------------------------------------------------------------
// TF32 mma.sync GEMM (NT): C[m,n] = sum_k A[m,k]*B[n,k] + bias[n]
// (unchanged from R3 — passing at ~97us each)
// ---------------------------------------------------------------------------
#define BM 128
#define BN 128
#define BKC 16
#define ASTR 20

__global__ __launch_bounds__(256) void gemm_tf32mma(
    const float* __restrict__ A, const float* __restrict__ B,
    const float* __restrict__ bias, float* __restrict__ C,
    int M, int N, int K)
{
    __shared__ uint32_t As[2][BM * ASTR];
    __shared__ uint32_t Bs[2][BN * ASTR];

    const int t    = threadIdx.x;
    const int wid  = t >> 5;
    const int lane = t & 31;
    const int mbase = blockIdx.y * BM;
    const int nbase = blockIdx.x * BN;

    const int lrow = t >> 1;
    const int lseg = (t & 1) * 8;
    const float* Ap = A + (size_t)(mbase + lrow) * K + lseg;
    const float* Bp = B + (size_t)(nbase + lrow) * K + lseg;
    const int sidx = lrow * ASTR + lseg;

    const int rm = (wid & 1) * 64;
    const int cn = (wid >> 1) * 32;
    const int lq = lane >> 2;
    const int lr4 = lane & 3;

    float acc[4][4][4];
#pragma unroll
    for (int mt = 0; mt < 4; mt++)
#pragma unroll
        for (int nt = 0; nt < 4; nt++)
#pragma unroll
            for (int i = 0; i < 4; i++) acc[mt][nt][i] = 0.f;

    const int NCH = K / BKC;

    {
        float4 a0 = *reinterpret_cast<const float4*>(Ap);
        float4 a1 = *reinterpret_cast<const float4*>(Ap + 4);
        float4 b0 = *reinterpret_cast<const float4*>(Bp);
        float4 b1 = *reinterpret_cast<const float4*>(Bp + 4);
        uint32_t* sa = &As[0][sidx];
        sa[0] = tf32_rn(a0.x); sa[1] = tf32_rn(a0.y); sa[2] = tf32_rn(a0.z); sa[3] = tf32_rn(a0.w);
        sa[4] = tf32_rn(a1.x); sa[5] = tf32_rn(a1.y); sa[6] = tf32_rn(a1.z); sa[7] = tf32_rn(a1.w);
        uint32_t* sb = &Bs[0][sidx];
        sb[0] = tf32_rn(b0.x); sb[1] = tf32_rn(b0.y); sb[2] = tf32_rn(b0.z); sb[3] = tf32_rn(b0.w);
        sb[4] = tf32_rn(b1.x); sb[5] = tf32_rn(b1.y); sb[6] = tf32_rn(b1.z); sb[7] = tf32_rn(b1.w);
    }
    __syncthreads();

    for (int c = 0; c < NCH; c++) {
        const int buf = c & 1;
        float4 pa0, pa1, pb0, pb1;
        if (c + 1 < NCH) {
            const float* ap = Ap + (c + 1) * BKC;
            const float* bp = Bp + (c + 1) * BKC;
            pa0 = *reinterpret_cast<const float4*>(ap);
            pa1 = *reinterpret_cast<const float4*>(ap + 4);
            pb0 = *reinterpret_cast<const float4*>(bp);
            pb1 = *reinterpret_cast<const float4*>(bp + 4);
        }

        const uint32_t* sA = As[buf];
        const uint32_t* sB = Bs[buf];
#pragma unroll
        for (int ks = 0; ks < 2; ks++) {
            const int k0 = ks * 8;
            uint32_t af[4][4], bf[4][2];
#pragma unroll
            for (int mt = 0; mt < 4; mt++) {
                const int r0 = rm + mt * 16;
                af[mt][0] = sA[(r0 + lq) * ASTR + k0 + lr4];
                af[mt][1] = sA[(r0 + 8 + lq) * ASTR + k0 + lr4];
                af[mt][2] = sA[(r0 + lq) * ASTR + k0 + 4 + lr4];
                af[mt][3] = sA[(r0 + 8 + lq) * ASTR + k0 + 4 + lr4];
            }
#pragma unroll
            for (int nt = 0; nt < 4; nt++) {
                const int c0 = cn + nt * 8;
                bf[nt][0] = sB[(c0 + lq) * ASTR + k0 + lr4];
                bf[nt][1] = sB[(c0 + lq) * ASTR + k0 + 4 + lr4];
            }
#pragma unroll
            for (int mt = 0; mt < 4; mt++)
#pragma unroll
                for (int nt = 0; nt < 4; nt++)
                    MMA_TF32(acc[mt][nt], af[mt][0], af[mt][1], af[mt][2], af[mt][3],
                             bf[nt][0], bf[nt][1]);
        }

        if (c + 1 < NCH) {
            uint32_t* sa = &As[buf ^ 1][sidx];
            sa[0] = tf32_rn(pa0.x); sa[1] = tf32_rn(pa0.y); sa[2] = tf32_rn(pa0.z); sa[3] = tf32_rn(pa0.w);
            sa[4] = tf32_rn(pa1.x); sa[5] = tf32_rn(pa1.y); sa[6] = tf32_rn(pa1.z); sa[7] = tf32_rn(pa1.w);
            uint32_t* sb = &Bs[buf ^ 1][sidx];
            sb[0] = tf32_rn(pb0.x); sb[1] = tf32_rn(pb0.y); sb[2] = tf32_rn(pb0.z); sb[3] = tf32_rn(pb0.w);
            sb[4] = tf32_rn(pb1.x); sb[5] = tf32_rn(pb1.y); sb[6] = tf32_rn(pb1.z); sb[7] = tf32_rn(pb1.w);
            __syncthreads();
        }
    }

#pragma unroll
    for (int mt = 0; mt < 4; mt++) {
        const int r0 = mbase + rm + mt * 16 + lq;
#pragma unroll
        for (int nt = 0; nt < 4; nt++) {
            const int col = nbase + cn + nt * 8 + lr4 * 2;
            const float bz0 = bias[col], bz1 = bias[col + 1];
            float2 v0 = make_float2(acc[mt][nt][0] + bz0, acc[mt][nt][1] + bz1);
            float2 v1 = make_float2(acc[mt][nt][2] + bz0, acc[mt][nt][3] + bz1);
            *reinterpret_cast<float2*>(&C[(size_t)r0 * N + col]) = v0;
            *reinterpret_cast<float2*>(&C[(size_t)(r0 + 8) * N + col]) = v1;
        }
    }
}

// ---------------------------------------------------------------------------
// Tensor-core flash attention (tf32 mma).
// grid (SEQ/128, NHEADS, BATCH) = (16,16,2), block 256 (8 warps).
// Warp w owns query rows [w*16, w*16+16). KV chunks of 64.
// smem strides chosen for conflict-free fragment LDS.
// ---------------------------------------------------------------------------
#define QT  128
#define KCH 64
#define QSTR 68
#define KSTR 68
#define VSTR 72
#define PSTR 68
// floats: Q 128*68=8704, K 64*68=4352, V 64*72=4608, P 128*68=8704 -> 26368
#define ATTN_SMEM_FLOATS (QT*QSTR + KCH*KSTR + KCH*VSTR + QT*PSTR)

__global__ __launch_bounds__(256) void attn_mma(
    const float* __restrict__ Q, const float* __restrict__ K,
    const float* __restrict__ V, float* __restrict__ O)
{
    extern __shared__ float sh[];
    float* Qs = sh;
    float* Ks = Qs + QT * QSTR;
    float* Vs = Ks + KCH * KSTR;
    float* Ps = Vs + KCH * VSTR;
    uint32_t* Qu = reinterpret_cast<uint32_t*>(Qs);
    uint32_t* Ku = reinterpret_cast<uint32_t*>(Ks);
    uint32_t* Vu = reinterpret_cast<uint32_t*>(Vs);
    uint32_t* Pu = reinterpret_cast<uint32_t*>(Ps);

    const int t    = threadIdx.x;
    const int wid  = t >> 5;
    const int lane = t & 31;
    const int lq   = lane >> 2;
    const int lr4  = lane & 3;

    const int qbase = blockIdx.x * QT;
    const int h     = blockIdx.y;
    const int b     = blockIdx.z;
    const int hbase = h * DK;

    // load Q tile (pre-scaled by 1/8, tf32-rounded): thread -> row t/2, 32-col half
    {
        const int lr = t >> 1;
        const int lc = (t & 1) * 32;
        const float* src = Q + ((size_t)b * SEQ + qbase + lr) * DMODEL + hbase + lc;
        uint32_t* dst = Qu + lr * QSTR + lc;
#pragma unroll
        for (int q4 = 0; q4 < 8; q4++) {
            float4 v4 = *reinterpret_cast<const float4*>(src + q4 * 4);
            dst[q4 * 4 + 0] = tf32_rn(v4.x * 0.125f);
            dst[q4 * 4 + 1] = tf32_rn(v4.y * 0.125f);
            dst[q4 * 4 + 2] = tf32_rn(v4.z * 0.125f);
            dst[q4 * 4 + 3] = tf32_rn(v4.w * 0.125f);
        }
    }

    const int qrow = wid * 16 + lq;   // first owned row inside tile

    float m0 = -1e30f, m1 = -1e30f, l0 = 0.f, l1 = 0.f;
    float oacc[8][4];
#pragma unroll
    for (int j = 0; j < 8; j++)
#pragma unroll
        for (int i = 0; i < 4; i++) oacc[j][i] = 0.f;

    // KV load map: thread -> row t/4, 16-col quarter
    const int klr = t >> 2;
    const int klc = (t & 3) * 16;

    for (int j0 = 0; j0 < SEQ; j0 += KCH) {
        // stage K,V chunk (tf32-rounded)
        {
            const size_t g = ((size_t)b * SEQ + j0 + klr) * DMODEL + hbase + klc;
            const float* ksrc = K + g;
            const float* vsrc = V + g;
            uint32_t* kdst = Ku + klr * KSTR + klc;
            uint32_t* vdst = Vu + klr * VSTR + klc;
#pragma unroll
            for (int q4 = 0; q4 < 4; q4++) {
                float4 vk = *reinterpret_cast<const float4*>(ksrc + q4 * 4);
                kdst[q4 * 4 + 0] = tf32_rn(vk.x);
                kdst[q4 * 4 + 1] = tf32_rn(vk.y);
                kdst[q4 * 4 + 2] = tf32_rn(vk.z);
                kdst[q4 * 4 + 3] = tf32_rn(vk.w);
                float4 vv = *reinterpret_cast<const float4*>(vsrc + q4 * 4);
                vdst[q4 * 4 + 0] = tf32_rn(vv.x);
                vdst[q4 * 4 + 1] = tf32_rn(vv.y);
                vdst[q4 * 4 + 2] = tf32_rn(vv.z);
                vdst[q4 * 4 + 3] = tf32_rn(vv.w);
            }
        }
        __syncthreads();

        // S = Q K^T : 8 n-tiles of kv, K=64 over 8 k-steps
        float s[8][4];
#pragma unroll
        for (int j = 0; j < 8; j++)
#pragma unroll
            for (int i = 0; i < 4; i++) s[j][i] = 0.f;

#pragma unroll
        for (int ks = 0; ks < 8; ks++) {
            const int k0 = ks * 8;
            uint32_t af0 = Qu[qrow * QSTR + k0 + lr4];
            uint32_t af1 = Qu[(qrow + 8) * QSTR + k0 + lr4];
            uint32_t af2 = Qu[qrow * QSTR + k0 + 4 + lr4];
            uint32_t af3 = Qu[(qrow + 8) * QSTR + k0 + 4 + lr4];
#pragma unroll
            for (int j = 0; j < 8; j++) {
                uint32_t bf0 = Ku[(j * 8 + lq) * KSTR + k0 + lr4];
                uint32_t bf1 = Ku[(j * 8 + lq) * KSTR + k0 + 4 + lr4];
                MMA_TF32(s[j], af0, af1, af2, af3, bf0, bf1);
            }
        }

        // online softmax for rows qrow (c0,c1) and qrow+8 (c2,c3)
        float mx0 = -1e30f, mx1 = -1e30f;
#pragma unroll
        for (int j = 0; j < 8; j++) {
            mx0 = fmaxf(mx0, fmaxf(s[j][0], s[j][1]));
            mx1 = fmaxf(mx1, fmaxf(s[j][2], s[j][3]));
        }
        mx0 = fmaxf(mx0, __shfl_xor_sync(0xffffffffu, mx0, 1));
        mx0 = fmaxf(mx0, __shfl_xor_sync(0xffffffffu, mx0, 2));
        mx1 = fmaxf(mx1, __shfl_xor_sync(0xffffffffu, mx1, 1));
        mx1 = fmaxf(mx1, __shfl_xor_sync(0xffffffffu, mx1, 2));

        const float m0n = fmaxf(m0, mx0);
        const float m1n = fmaxf(m1, mx1);
        const float a0 = __expf(m0 - m0n);
        const float a1 = __expf(m1 - m1n);
        m0 = m0n; m1 = m1n;

        float rs0 = 0.f, rs1 = 0.f;
#pragma unroll
        for (int j = 0; j < 8; j++) {
            float p0 = __expf(s[j][0] - m0);
            float p1 = __expf(s[j][1] - m0);
            float p2 = __expf(s[j][2] - m1);
            float p3 = __expf(s[j][3] - m1);
            rs0 += p0 + p1;
            rs1 += p2 + p3;
            const int cb = j * 8 + 2 * lr4;
            Pu[qrow * PSTR + cb]           = tf32_rn(p0);
            Pu[qrow * PSTR + cb + 1]       = tf32_rn(p1);
            Pu[(qrow + 8) * PSTR + cb]     = tf32_rn(p2);
            Pu[(qrow + 8) * PSTR + cb + 1] = tf32_rn(p3);
        }
        rs0 += __shfl_xor_sync(0xffffffffu, rs0, 1);
        rs0 += __shfl_xor_sync(0xffffffffu, rs0, 2);
        rs1 += __shfl_xor_sync(0xffffffffu, rs1, 1);
        rs1 += __shfl_xor_sync(0xffffffffu, rs1, 2);
        l0 = l0 * a0 + rs0;
        l1 = l1 * a1 + rs1;
#pragma unroll
        for (int j = 0; j < 8; j++) {
            oacc[j][0] *= a0; oacc[j][1] *= a0;
            oacc[j][2] *= a1; oacc[j][3] *= a1;
        }
        __syncwarp();

        // O += P V : k dim = 64 kv positions, 8 n-tiles over dk
#pragma unroll
        for (int ks = 0; ks < 8; ks++) {
            const int k0 = ks * 8;
            uint32_t af0 = Pu[qrow * PSTR + k0 + lr4];
            uint32_t af1 = Pu[(qrow + 8) * PSTR + k0 + lr4];
            uint32_t af2 = Pu[qrow * PSTR + k0 + 4 + lr4];
            uint32_t af3 = Pu[(qrow + 8) * PSTR + k0 + 4 + lr4];
#pragma unroll
            for (int j = 0; j < 8; j++) {
                uint32_t bf0 = Vu[(k0 + lr4) * VSTR + j * 8 + lq];
                uint32_t bf1 = Vu[(k0 + 4 + lr4) * VSTR + j * 8 + lq];
                MMA_TF32(oacc[j], af0, af1, af2, af3, bf0, bf1);
            }
        }
        __syncthreads();
    }

    // finalize
    const float inv0 = 1.f / l0;
    const float inv1 = 1.f / l1;
    const size_t row0 = (size_t)b * SEQ + qbase + qrow;
#pragma unroll
    for (int j = 0; j < 8; j++) {
        const int col = hbase + j * 8 + 2 * lr4;
        float2 v0 = make_float2(oacc[j][0] * inv0, oacc[j][1] * inv0);
        float2 v1 = make_float2(oacc[j][2] * inv1, oacc[j][3] * inv1);
        *reinterpret_cast<float2*>(&O[row0 * DMODEL + col]) = v0;
        *reinterpret_cast<float2*>(&O[(row0 + 8) * DMODEL + col]) = v1;
    }
}

// ---------------------------------------------------------------------------
// launch
// ---------------------------------------------------------------------------
extern "C" void kernel_launch(void* const* d_in, const int* in_sizes, int n_in,
                              void* d_out, int out_size)
{
    const float* q   = (const float*)d_in[0];
    const float* k   = (const float*)d_in[1];
    const float* v   = (const float*)d_in[2];
    const float* W_q = (const float*)d_in[3];
    const float* b_q = (const float*)d_in[4];
    const float* W_k = (const float*)d_in[5];
    const float* b_k = (const float*)d_in[6];
    const float* W_v = (const float*)d_in[7];
    const float* b_v = (const float*)d_in[8];
    const float* W_o = (const float*)d_in[9];
    const float* b_o = (const float*)d_in[10];
    float* out = (float*)d_out;

    float *Qp, *Kp, *Vp, *Op;
    cudaGetSymbolAddress((void**)&Qp, g_Q);
    cudaGetSymbolAddress((void**)&Kp, g_K);
    cudaGetSymbolAddress((void**)&Vp, g_V);
    cudaGetSymbolAddress((void**)&Op, g_O);

    dim3 ggrid(DMODEL / BN, MROWS / BM);   // (8, 32)

    gemm_tf32mma<<<ggrid, 256>>>(q, W_q, b_q, Qp, MROWS, DMODEL, DMODEL);
    gemm_tf32mma<<<ggrid, 256>>>(k, W_k, b_k, Kp, MROWS, DMODEL, DMODEL);
    gemm_tf32mma<<<ggrid, 256>>>(v, W_v, b_v, Vp, MROWS, DMODEL, DMODEL);

    const size_t ashm = ATTN_SMEM_FLOATS * sizeof(float);  // 105472
    cudaFuncSetAttribute(attn_mma, cudaFuncAttributeMaxDynamicSharedMemorySize, (int)ashm);
    dim3 agrid(SEQ / QT, NHEADS, BATCH);   // (16, 16, 2)
    attn_mma<<<agrid, dim3(256), ashm>>>(Qp, Kp, Vp, Op);

    gemm_tf32mma<<<ggrid, 256>>>(Op, W_o, b_o, out, MROWS, DMODEL, DMODEL);
    (void)in_sizes; (void)n_in; (void)out_size;
}

// round 5
// speedup vs baseline: 2.9034x; 1.0114x over previous
#include <cuda_runtime.h>
#include <cuda_bf16.h>
#include <cstdint>
#include <math.h>

// Problem constants
#define BATCH 2
#define SEQ   2048
#define DMODEL 1024
#define NHEADS 16
#define DK    64
#define MROWS (BATCH*SEQ)   // 4096

// ---------------------------------------------------------------------------
// Scratch
// ---------------------------------------------------------------------------
__device__ float g_Q[MROWS * DMODEL];
__device__ float g_K[MROWS * DMODEL];
__device__ float g_V[MROWS * DMODEL];
__device__ float g_O[MROWS * DMODEL];

__device__ __forceinline__ uint32_t tf32_rn(float x) {
    uint32_t y; asm("cvt.rna.tf32.f32 %0, %1;" : "=r"(y) : "f"(x));
    return y;
}

#define MMA_TF32(d, a0,a1,a2,a3, b0,b1) \
    asm volatile( \
        "mma.sync.aligned.m16n8k8.row.col.f32.tf32.tf32.f32 " \
        "{%0,%1,%2,%3}, {%4,%5,%6,%7}, {%8,%9}, {%0,%1,%2,%3};" \
        : "+f"((d)[0]), "+f"((d)[1]), "+f"((d)[2]), "+f"((d)[3]) \
        : "r"(a0), "r"(a1), "r"(a2), "r"(a3), "r"(b0), "r"(b1))

// ---------------------------------------------------------------------------
// TF32 mma.sync GEMM body (NT): C[m,n] = sum_k A[m,k]*B[n,k] + bias[n]
// ---------------------------------------------------------------------------
#define BM 128
#define BN 128
#define BKC 16
#define ASTR 20

__device__ __forceinline__ void gemm_body(
    const float* __restrict__ A, const float* __restrict__ B,
    const float* __restrict__ bias, float* __restrict__ C,
    int M, int N, int K,
    uint32_t (*As)[BM * ASTR], uint32_t (*Bs)[BN * ASTR])
{
    const int t    = threadIdx.x;
    const int wid  = t >> 5;
    const int lane = t & 31;
    const int mbase = blockIdx.y * BM;
    const int nbase = blockIdx.x * BN;

    const int lrow = t >> 1;
    const int lseg = (t & 1) * 8;
    const float* Ap = A + (size_t)(mbase + lrow) * K + lseg;
    const float* Bp = B + (size_t)(nbase + lrow) * K + lseg;
    const int sidx = lrow * ASTR + lseg;

    const int rm = (wid & 1) * 64;
    const int cn = (wid >> 1) * 32;
    const int lq = lane >> 2;
    const int lr4 = lane & 3;

    float acc[4][4][4];
#pragma unroll
    for (int mt = 0; mt < 4; mt++)
#pragma unroll
        for (int nt = 0; nt < 4; nt++)
#pragma unroll
            for (int i = 0; i < 4; i++) acc[mt][nt][i] = 0.f;

    const int NCH = K / BKC;

    {
        float4 a0 = *reinterpret_cast<const float4*>(Ap);
        float4 a1 = *reinterpret_cast<const float4*>(Ap + 4);
        float4 b0 = *reinterpret_cast<const float4*>(Bp);
        float4 b1 = *reinterpret_cast<const float4*>(Bp + 4);
        uint32_t* sa = &As[0][sidx];
        sa[0] = tf32_rn(a0.x); sa[1] = tf32_rn(a0.y); sa[2] = tf32_rn(a0.z); sa[3] = tf32_rn(a0.w);
        sa[4] = tf32_rn(a1.x); sa[5] = tf32_rn(a1.y); sa[6] = tf32_rn(a1.z); sa[7] = tf32_rn(a1.w);
        uint32_t* sb = &Bs[0][sidx];
        sb[0] = tf32_rn(b0.x); sb[1] = tf32_rn(b0.y); sb[2] = tf32_rn(b0.z); sb[3] = tf32_rn(b0.w);
        sb[4] = tf32_rn(b1.x); sb[5] = tf32_rn(b1.y); sb[6] = tf32_rn(b1.z); sb[7] = tf32_rn(b1.w);
    }
    __syncthreads();

    for (int c = 0; c < NCH; c++) {
        const int buf = c & 1;
        float4 pa0, pa1, pb0, pb1;
        if (c + 1 < NCH) {
            const float* ap = Ap + (c + 1) * BKC;
            const float* bp = Bp + (c + 1) * BKC;
            pa0 = *reinterpret_cast<const float4*>(ap);
            pa1 = *reinterpret_cast<const float4*>(ap + 4);
            pb0 = *reinterpret_cast<const float4*>(bp);
            pb1 = *reinterpret_cast<const float4*>(bp + 4);
        }

        const uint32_t* sA = As[buf];
        const uint32_t* sB = Bs[buf];
#pragma unroll
        for (int ks = 0; ks < 2; ks++) {
            const int k0 = ks * 8;
            uint32_t af[4][4], bf[4][2];
#pragma unroll
            for (int mt = 0; mt < 4; mt++) {
                const int r0 = rm + mt * 16;
                af[mt][0] = sA[(r0 + lq) * ASTR + k0 + lr4];
                af[mt][1] = sA[(r0 + 8 + lq) * ASTR + k0 + lr4];
                af[mt][2] = sA[(r0 + lq) * ASTR + k0 + 4 + lr4];
                af[mt][3] = sA[(r0 + 8 + lq) * ASTR + k0 + 4 + lr4];
            }
#pragma unroll
            for (int nt = 0; nt < 4; nt++) {
                const int c0 = cn + nt * 8;
                bf[nt][0] = sB[(c0 + lq) * ASTR + k0 + lr4];
                bf[nt][1] = sB[(c0 + lq) * ASTR + k0 + 4 + lr4];
            }
#pragma unroll
            for (int mt = 0; mt < 4; mt++)
#pragma unroll
                for (int nt = 0; nt < 4; nt++)
                    MMA_TF32(acc[mt][nt], af[mt][0], af[mt][1], af[mt][2], af[mt][3],
                             bf[nt][0], bf[nt][1]);
        }

        if (c + 1 < NCH) {
            uint32_t* sa = &As[buf ^ 1][sidx];
            sa[0] = tf32_rn(pa0.x); sa[1] = tf32_rn(pa0.y); sa[2] = tf32_rn(pa0.z); sa[3] = tf32_rn(pa0.w);
            sa[4] = tf32_rn(pa1.x); sa[5] = tf32_rn(pa1.y); sa[6] = tf32_rn(pa1.z); sa[7] = tf32_rn(pa1.w);
            uint32_t* sb = &Bs[buf ^ 1][sidx];
            sb[0] = tf32_rn(pb0.x); sb[1] = tf32_rn(pb0.y); sb[2] = tf32_rn(pb0.z); sb[3] = tf32_rn(pb0.w);
            sb[4] = tf32_rn(pb1.x); sb[5] = tf32_rn(pb1.y); sb[6] = tf32_rn(pb1.z); sb[7] = tf32_rn(pb1.w);
            __syncthreads();
        }
    }

#pragma unroll
    for (int mt = 0; mt < 4; mt++) {
        const int r0 = mbase + rm + mt * 16 + lq;
#pragma unroll
        for (int nt = 0; nt < 4; nt++) {
            const int col = nbase + cn + nt * 8 + lr4 * 2;
            const float bz0 = bias[col], bz1 = bias[col + 1];
            float2 v0 = make_float2(acc[mt][nt][0] + bz0, acc[mt][nt][1] + bz1);
            float2 v1 = make_float2(acc[mt][nt][2] + bz0, acc[mt][nt][3] + bz1);
            *reinterpret_cast<float2*>(&C[(size_t)r0 * N + col]) = v0;
            *reinterpret_cast<float2*>(&C[(size_t)(r0 + 8) * N + col]) = v1;
        }
    }
}

// Fused Q/K/V projection: grid.z in {0,1,2} selects the operand triple.
__global__ __launch_bounds__(256) void gemm_qkv(
    const float* __restrict__ Aq, const float* __restrict__ Ak, const float* __restrict__ Av,
    const float* __restrict__ Wq, const float* __restrict__ Wk, const float* __restrict__ Wv,
    const float* __restrict__ bq, const float* __restrict__ bk, const float* __restrict__ bv,
    float* __restrict__ Cq, float* __restrict__ Ck, float* __restrict__ Cv)
{
    __shared__ uint32_t As[2][BM * ASTR];
    __shared__ uint32_t Bs[2][BN * ASTR];
    const int z = blockIdx.z;
    const float* A = (z == 0) ? Aq : (z == 1) ? Ak : Av;
    const float* W = (z == 0) ? Wq : (z == 1) ? Wk : Wv;
    const float* bi = (z == 0) ? bq : (z == 1) ? bk : bv;
    float* C = (z == 0) ? Cq : (z == 1) ? Ck : Cv;
    gemm_body(A, W, bi, C, MROWS, DMODEL, DMODEL, As, Bs);
}

__global__ __launch_bounds__(256) void gemm_tf32mma(
    const float* __restrict__ A, const float* __restrict__ B,
    const float* __restrict__ bias, float* __restrict__ C,
    int M, int N, int K)
{
    __shared__ uint32_t As[2][BM * ASTR];
    __shared__ uint32_t Bs[2][BN * ASTR];
    gemm_body(A, B, bias, C, M, N, K, As, Bs);
}

// ---------------------------------------------------------------------------
// Tensor-core flash attention (tf32 mma), 2 CTAs/SM residency.
// grid (SEQ/128, NHEADS, BATCH) = (16,16,2), block 256 (8 warps).
// ---------------------------------------------------------------------------
#define QT  128
#define KCH 64
#define QSTR 68
#define KSTR 68
#define VSTR 72
#define PSTR 68
#define ATTN_SMEM_FLOATS (QT*QSTR + KCH*KSTR + KCH*VSTR + QT*PSTR)  // 26368

__global__ __launch_bounds__(256, 2) void attn_mma(
    const float* __restrict__ Q, const float* __restrict__ K,
    const float* __restrict__ V, float* __restrict__ O)
{
    extern __shared__ float sh[];
    float* Qs = sh;
    float* Ks = Qs + QT * QSTR;
    float* Vs = Ks + KCH * KSTR;
    float* Ps = Vs + KCH * VSTR;
    uint32_t* Qu = reinterpret_cast<uint32_t*>(Qs);
    uint32_t* Ku = reinterpret_cast<uint32_t*>(Ks);
    uint32_t* Vu = reinterpret_cast<uint32_t*>(Vs);
    uint32_t* Pu = reinterpret_cast<uint32_t*>(Ps);

    const int t    = threadIdx.x;
    const int wid  = t >> 5;
    const int lane = t & 31;
    const int lq   = lane >> 2;
    const int lr4  = lane & 3;

    const int qbase = blockIdx.x * QT;
    const int h     = blockIdx.y;
    const int b     = blockIdx.z;
    const int hbase = h * DK;

    // load Q tile (pre-scaled by 1/8, tf32-rounded)
    {
        const int lr = t >> 1;
        const int lc = (t & 1) * 32;
        const float* src = Q + ((size_t)b * SEQ + qbase + lr) * DMODEL + hbase + lc;
        uint32_t* dst = Qu + lr * QSTR + lc;
#pragma unroll
        for (int q4 = 0; q4 < 8; q4++) {
            float4 v4 = *reinterpret_cast<const float4*>(src + q4 * 4);
            dst[q4 * 4 + 0] = tf32_rn(v4.x * 0.125f);
            dst[q4 * 4 + 1] = tf32_rn(v4.y * 0.125f);
            dst[q4 * 4 + 2] = tf32_rn(v4.z * 0.125f);
            dst[q4 * 4 + 3] = tf32_rn(v4.w * 0.125f);
        }
    }

    const int qrow = wid * 16 + lq;

    float m0 = -1e30f, m1 = -1e30f, l0 = 0.f, l1 = 0.f;
    float oacc[8][4];
#pragma unroll
    for (int j = 0; j < 8; j++)
#pragma unroll
        for (int i = 0; i < 4; i++) oacc[j][i] = 0.f;

    const int klr = t >> 2;
    const int klc = (t & 3) * 16;

    for (int j0 = 0; j0 < SEQ; j0 += KCH) {
        {
            const size_t g = ((size_t)b * SEQ + j0 + klr) * DMODEL + hbase + klc;
            const float* ksrc = K + g;
            const float* vsrc = V + g;
            uint32_t* kdst = Ku + klr * KSTR + klc;
            uint32_t* vdst = Vu + klr * VSTR + klc;
#pragma unroll
            for (int q4 = 0; q4 < 4; q4++) {
                float4 vk = *reinterpret_cast<const float4*>(ksrc + q4 * 4);
                kdst[q4 * 4 + 0] = tf32_rn(vk.x);
                kdst[q4 * 4 + 1] = tf32_rn(vk.y);
                kdst[q4 * 4 + 2] = tf32_rn(vk.z);
                kdst[q4 * 4 + 3] = tf32_rn(vk.w);
                float4 vv = *reinterpret_cast<const float4*>(vsrc + q4 * 4);
                vdst[q4 * 4 + 0] = tf32_rn(vv.x);
                vdst[q4 * 4 + 1] = tf32_rn(vv.y);
                vdst[q4 * 4 + 2] = tf32_rn(vv.z);
                vdst[q4 * 4 + 3] = tf32_rn(vv.w);
            }
        }
        __syncthreads();

        float s[8][4];
#pragma unroll
        for (int j = 0; j < 8; j++)
#pragma unroll
            for (int i = 0; i < 4; i++) s[j][i] = 0.f;

#pragma unroll
        for (int ks = 0; ks < 8; ks++) {
            const int k0 = ks * 8;
            uint32_t af0 = Qu[qrow * QSTR + k0 + lr4];
            uint32_t af1 = Qu[(qrow + 8) * QSTR + k0 + lr4];
            uint32_t af2 = Qu[qrow * QSTR + k0 + 4 + lr4];
            uint32_t af3 = Qu[(qrow + 8) * QSTR + k0 + 4 + lr4];
#pragma unroll
            for (int j = 0; j < 8; j++) {
                uint32_t bf0 = Ku[(j * 8 + lq) * KSTR + k0 + lr4];
                uint32_t bf1 = Ku[(j * 8 + lq) * KSTR + k0 + 4 + lr4];
                MMA_TF32(s[j], af0, af1, af2, af3, bf0, bf1);
            }
        }

        float mx0 = -1e30f, mx1 = -1e30f;
#pragma unroll
        for (int j = 0; j < 8; j++) {
            mx0 = fmaxf(mx0, fmaxf(s[j][0], s[j][1]));
            mx1 = fmaxf(mx1, fmaxf(s[j][2], s[j][3]));
        }
        mx0 = fmaxf(mx0, __shfl_xor_sync(0xffffffffu, mx0, 1));
        mx0 = fmaxf(mx0, __shfl_xor_sync(0xffffffffu, mx0, 2));
        mx1 = fmaxf(mx1, __shfl_xor_sync(0xffffffffu, mx1, 1));
        mx1 = fmaxf(mx1, __shfl_xor_sync(0xffffffffu, mx1, 2));

        const float m0n = fmaxf(m0, mx0);
        const float m1n = fmaxf(m1, mx1);
        const float a0 = __expf(m0 - m0n);
        const float a1 = __expf(m1 - m1n);
        m0 = m0n; m1 = m1n;

        float rs0 = 0.f, rs1 = 0.f;
#pragma unroll
        for (int j = 0; j < 8; j++) {
            float p0 = __expf(s[j][0] - m0);
            float p1 = __expf(s[j][1] - m0);
            float p2 = __expf(s[j][2] - m1);
            float p3 = __expf(s[j][3] - m1);
            rs0 += p0 + p1;
            rs1 += p2 + p3;
            const int cb = j * 8 + 2 * lr4;
            Pu[qrow * PSTR + cb]           = tf32_rn(p0);
            Pu[qrow * PSTR + cb + 1]       = tf32_rn(p1);
            Pu[(qrow + 8) * PSTR + cb]     = tf32_rn(p2);
            Pu[(qrow + 8) * PSTR + cb + 1] = tf32_rn(p3);
        }
        rs0 += __shfl_xor_sync(0xffffffffu, rs0, 1);
        rs0 += __shfl_xor_sync(0xffffffffu, rs0, 2);
        rs1 += __shfl_xor_sync(0xffffffffu, rs1, 1);
        rs1 += __shfl_xor_sync(0xffffffffu, rs1, 2);
        l0 = l0 * a0 + rs0;
        l1 = l1 * a1 + rs1;
#pragma unroll
        for (int j = 0; j < 8; j++) {
            oacc[j][0] *= a0; oacc[j][1] *= a0;
            oacc[j][2] *= a1; oacc[j][3] *= a1;
        }
        __syncwarp();

#pragma unroll
        for (int ks = 0; ks < 8; ks++) {
            const int k0 = ks * 8;
            uint32_t af0 = Pu[qrow * PSTR + k0 + lr4];
            uint32_t af1 = Pu[(qrow + 8) * PSTR + k0 + lr4];
            uint32_t af2 = Pu[qrow * PSTR + k0 + 4 + lr4];
            uint32_t af3 = Pu[(qrow + 8) * PSTR + k0 + 4 + lr4];
#pragma unroll
            for (int j = 0; j < 8; j++) {
                uint32_t bf0 = Vu[(k0 + lr4) * VSTR + j * 8 + lq];
                uint32_t bf1 = Vu[(k0 + 4 + lr4) * VSTR + j * 8 + lq];
                MMA_TF32(oacc[j], af0, af1, af2, af3, bf0, bf1);
            }
        }
        __syncthreads();
    }

    const float inv0 = 1.f / l0;
    const float inv1 = 1.f / l1;
    const size_t row0 = (size_t)b * SEQ + qbase + qrow;
#pragma unroll
    for (int j = 0; j < 8; j++) {
        const int col = hbase + j * 8 + 2 * lr4;
        float2 v0 = make_float2(oacc[j][0] * inv0, oacc[j][1] * inv0);
        float2 v1 = make_float2(oacc[j][2] * inv1, oacc[j][3] * inv1);
        *reinterpret_cast<float2*>(&O[row0 * DMODEL + col]) = v0;
        *reinterpret_cast<float2*>(&O[(row0 + 8) * DMODEL + col]) = v1;
    }
}

// ---------------------------------------------------------------------------
// launch
// ---------------------------------------------------------------------------
extern "C" void kernel_launch(void* const* d_in, const int* in_sizes, int n_in,
                              void* d_out, int out_size)
{
    const float* q   = (const float*)d_in[0];
    const float* k   = (const float*)d_in[1];
    const float* v   = (const float*)d_in[2];
    const float* W_q = (const float*)d_in[3];
    const float* b_q = (const float*)d_in[4];
    const float* W_k = (const float*)d_in[5];
    const float* b_k = (const float*)d_in[6];
    const float* W_v = (const float*)d_in[7];
    const float* b_v = (const float*)d_in[8];
    const float* W_o = (const float*)d_in[9];
    const float* b_o = (const float*)d_in[10];
    float* out = (float*)d_out;

    float *Qp, *Kp, *Vp, *Op;
    cudaGetSymbolAddress((void**)&Qp, g_Q);
    cudaGetSymbolAddress((void**)&Kp, g_K);
    cudaGetSymbolAddress((void**)&Vp, g_V);
    cudaGetSymbolAddress((void**)&Op, g_O);

    // fused Q/K/V projections: one launch, grid.z selects
    dim3 qkvgrid(DMODEL / BN, MROWS / BM, 3);   // (8, 32, 3)
    gemm_qkv<<<qkvgrid, 256>>>(q, k, v, W_q, W_k, W_v, b_q, b_k, b_v, Qp, Kp, Vp);

    const size_t ashm = ATTN_SMEM_FLOATS * sizeof(float);  // 105472
    cudaFuncSetAttribute(attn_mma, cudaFuncAttributeMaxDynamicSharedMemorySize, (int)ashm);
    dim3 agrid(SEQ / QT, NHEADS, BATCH);   // (16, 16, 2)
    attn_mma<<<agrid, dim3(256), ashm>>>(Qp, Kp, Vp, Op);

    dim3 ggrid(DMODEL / BN, MROWS / BM);   // (8, 32)
    gemm_tf32mma<<<ggrid, 256>>>(Op, W_o, b_o, out, MROWS, DMODEL, DMODEL);
    (void)in_sizes; (void)n_in; (void)out_size;
}

// round 6
// speedup vs baseline: 3.2871x; 1.1322x over previous
#include <cuda_runtime.h>
#include <cuda_bf16.h>
#include <cstdint>
#include <math.h>

#define BATCH 2
#define SEQ   2048
#define DMODEL 1024
#define NHEADS 16
#define DK    64
#define MROWS (BATCH*SEQ)   // 4096

// ---------------------------------------------------------------------------
// Scratch (tf32-pre-rounded operands + intermediates)
// ---------------------------------------------------------------------------
__device__ __align__(128) float g_Q[MROWS * DMODEL];
__device__ __align__(128) float g_K[MROWS * DMODEL];
__device__ __align__(128) float g_V[MROWS * DMODEL];
__device__ __align__(128) float g_O[MROWS * DMODEL];
__device__ __align__(128) float g_Xq[MROWS * DMODEL];
__device__ __align__(128) float g_Xk[MROWS * DMODEL];
__device__ __align__(128) float g_Xv[MROWS * DMODEL];
__device__ __align__(128) float g_Wq[DMODEL * DMODEL];
__device__ __align__(128) float g_Wk[DMODEL * DMODEL];
__device__ __align__(128) float g_Wv[DMODEL * DMODEL];
__device__ __align__(128) float g_Wo[DMODEL * DMODEL];

__device__ __forceinline__ uint32_t tf32_rn(float x) {
    uint32_t y; asm("cvt.rna.tf32.f32 %0, %1;" : "=r"(y) : "f"(x));
    return y;
}
__device__ __forceinline__ float tf32f(float x) { return __uint_as_float(tf32_rn(x)); }

__device__ __forceinline__ uint32_t smem_u32(const void* p) {
    uint32_t a;
    asm("{ .reg .u64 t; cvta.to.shared.u64 t, %1; cvt.u32.u64 %0, t; }" : "=r"(a) : "l"(p));
    return a;
}
__device__ __forceinline__ void cp16(uint32_t dst, const float* src) {
    asm volatile("cp.async.cg.shared.global [%0], [%1], 16;" :: "r"(dst), "l"(src));
}
#define CP_COMMIT() asm volatile("cp.async.commit_group;" ::: "memory")
#define CP_WAIT(n)  asm volatile("cp.async.wait_group %0;" :: "n"(n) : "memory")

#define MMA_TF32(d, a0,a1,a2,a3, b0,b1) \
    asm volatile( \
        "mma.sync.aligned.m16n8k8.row.col.f32.tf32.tf32.f32 " \
        "{%0,%1,%2,%3}, {%4,%5,%6,%7}, {%8,%9}, {%0,%1,%2,%3};" \
        : "+f"((d)[0]), "+f"((d)[1]), "+f"((d)[2]), "+f"((d)[3]) \
        : "r"(a0), "r"(a1), "r"(a2), "r"(a3), "r"(b0), "r"(b1))

// ---------------------------------------------------------------------------
// Pre-pass: rna-round inputs and weights into scratch (bit-identical to
// rounding at GEMM staging time).  grid (x, 7), block 256, float4 strided.
// ---------------------------------------------------------------------------
__global__ __launch_bounds__(256) void prepass(
    const float* __restrict__ q, const float* __restrict__ k, const float* __restrict__ v,
    const float* __restrict__ Wq, const float* __restrict__ Wk,
    const float* __restrict__ Wv, const float* __restrict__ Wo)
{
    const float* src; float* dst; int n4;
    switch (blockIdx.y) {
        case 0: src = q;  dst = g_Xq; n4 = MROWS * DMODEL / 4; break;
        case 1: src = k;  dst = g_Xk; n4 = MROWS * DMODEL / 4; break;
        case 2: src = v;  dst = g_Xv; n4 = MROWS * DMODEL / 4; break;
        case 3: src = Wq; dst = g_Wq; n4 = DMODEL * DMODEL / 4; break;
        case 4: src = Wk; dst = g_Wk; n4 = DMODEL * DMODEL / 4; break;
        case 5: src = Wv; dst = g_Wv; n4 = DMODEL * DMODEL / 4; break;
        default: src = Wo; dst = g_Wo; n4 = DMODEL * DMODEL / 4; break;
    }
    for (int i = blockIdx.x * blockDim.x + threadIdx.x; i < n4; i += gridDim.x * blockDim.x) {
        float4 t = reinterpret_cast<const float4*>(src)[i];
        t.x = tf32f(t.x); t.y = tf32f(t.y); t.z = tf32f(t.z); t.w = tf32f(t.w);
        reinterpret_cast<float4*>(dst)[i] = t;
    }
}

// ---------------------------------------------------------------------------
// TF32 mma GEMM v2 (NT): C[m,n] = sum_k A[m,k]*B[n,k] + bias[n]
// CTA 128x256, 8 warps of 64x64, K-chunk 16, 3-stage cp.async.
// A,B must be tf32-pre-rounded.  mode: 0 plain fp32 out, 1 tf32 out, 2 tf32*0.125
// ---------------------------------------------------------------------------
#define GBM 128
#define GBN 256
#define GBK 16
#define GSTG 3
#define GSTR 20
#define GA_FLOATS (GBM * GSTR)            // 2560
#define GB_FLOATS (GBN * GSTR)            // 5120
#define GEMM_SMEM ((GSTG * (GA_FLOATS + GB_FLOATS)) * 4)  // 92160 B

__device__ __forceinline__ void gemm2_body(
    const float* __restrict__ A, const float* __restrict__ B,
    const float* __restrict__ bias, float* __restrict__ C,
    int M, int N, int K, int mode, float* sm)
{
    float* As = sm;
    float* Bs = sm + GSTG * GA_FLOATS;

    const int t    = threadIdx.x;
    const int wid  = t >> 5;
    const int lane = t & 31;
    const int lq   = lane >> 2;
    const int lr4  = lane & 3;
    const int mbase = blockIdx.y * GBM;
    const int nbase = blockIdx.x * GBN;

    // cp.async maps
    const int arow = t >> 1, aseg = (t & 1) * 8;
    const float* Ap = A + (size_t)(mbase + arow) * K + aseg;
    const uint32_t a_s = smem_u32(As) + (arow * GSTR + aseg) * 4;
    const float* Bp = B + (size_t)(nbase + t) * K;
    const uint32_t b_s = smem_u32(Bs) + (t * GSTR) * 4;
    const uint32_t ssa = GA_FLOATS * 4, ssb = GB_FLOATS * 4;

    const int NCH = K / GBK;   // 64

#define G2_ISSUE(c, s) { \
        const float* ap_ = Ap + (c) * GBK; \
        cp16(a_s + (s) * ssa, ap_); cp16(a_s + (s) * ssa + 16, ap_ + 4); \
        const float* bp_ = Bp + (c) * GBK; \
        cp16(b_s + (s) * ssb, bp_);      cp16(b_s + (s) * ssb + 16, bp_ + 4); \
        cp16(b_s + (s) * ssb + 32, bp_ + 8); cp16(b_s + (s) * ssb + 48, bp_ + 12); }

    G2_ISSUE(0, 0); CP_COMMIT();
    G2_ISSUE(1, 1); CP_COMMIT();

    const int rm = (wid & 1) * 64;
    const int cn = (wid >> 1) * 64;

    float acc[4][8][4];
#pragma unroll
    for (int mt = 0; mt < 4; mt++)
#pragma unroll
        for (int nt = 0; nt < 8; nt++)
#pragma unroll
            for (int i = 0; i < 4; i++) acc[mt][nt][i] = 0.f;

    for (int c = 0; c < NCH; c++) {
        CP_WAIT(1);
        __syncthreads();
        const int buf = c % GSTG;
        const uint32_t* sA = reinterpret_cast<const uint32_t*>(As + buf * GA_FLOATS);
        const uint32_t* sB = reinterpret_cast<const uint32_t*>(Bs + buf * GB_FLOATS);
#pragma unroll
        for (int ks = 0; ks < 2; ks++) {
            const int k0 = ks * 8;
            uint32_t af[4][4], bf[8][2];
#pragma unroll
            for (int mt = 0; mt < 4; mt++) {
                const int r0 = rm + mt * 16;
                af[mt][0] = sA[(r0 + lq) * GSTR + k0 + lr4];
                af[mt][1] = sA[(r0 + 8 + lq) * GSTR + k0 + lr4];
                af[mt][2] = sA[(r0 + lq) * GSTR + k0 + 4 + lr4];
                af[mt][3] = sA[(r0 + 8 + lq) * GSTR + k0 + 4 + lr4];
            }
#pragma unroll
            for (int nt = 0; nt < 8; nt++) {
                const int c0 = cn + nt * 8;
                bf[nt][0] = sB[(c0 + lq) * GSTR + k0 + lr4];
                bf[nt][1] = sB[(c0 + lq) * GSTR + k0 + 4 + lr4];
            }
#pragma unroll
            for (int mt = 0; mt < 4; mt++)
#pragma unroll
                for (int nt = 0; nt < 8; nt++)
                    MMA_TF32(acc[mt][nt], af[mt][0], af[mt][1], af[mt][2], af[mt][3],
                             bf[nt][0], bf[nt][1]);
        }
        if (c + 2 < NCH) { G2_ISSUE(c + 2, (c + 2) % GSTG); }
        CP_COMMIT();
    }
#undef G2_ISSUE

#pragma unroll
    for (int mt = 0; mt < 4; mt++) {
        const int r0 = mbase + rm + mt * 16 + lq;
#pragma unroll
        for (int nt = 0; nt < 8; nt++) {
            const int col = nbase + cn + nt * 8 + lr4 * 2;
            const float bz0 = bias[col], bz1 = bias[col + 1];
            float v00 = acc[mt][nt][0] + bz0, v01 = acc[mt][nt][1] + bz1;
            float v10 = acc[mt][nt][2] + bz0, v11 = acc[mt][nt][3] + bz1;
            if (mode == 2) {
                v00 = tf32f(v00 * 0.125f); v01 = tf32f(v01 * 0.125f);
                v10 = tf32f(v10 * 0.125f); v11 = tf32f(v11 * 0.125f);
            } else if (mode == 1) {
                v00 = tf32f(v00); v01 = tf32f(v01);
                v10 = tf32f(v10); v11 = tf32f(v11);
            }
            *reinterpret_cast<float2*>(&C[(size_t)r0 * N + col]) = make_float2(v00, v01);
            *reinterpret_cast<float2*>(&C[(size_t)(r0 + 8) * N + col]) = make_float2(v10, v11);
        }
    }
}

__global__ __launch_bounds__(256, 1) void gemm_qkv(
    const float* __restrict__ bq, const float* __restrict__ bk, const float* __restrict__ bv)
{
    extern __shared__ float sm[];
    const int z = blockIdx.z;
    const float* A  = (z == 0) ? g_Xq : (z == 1) ? g_Xk : g_Xv;
    const float* B  = (z == 0) ? g_Wq : (z == 1) ? g_Wk : g_Wv;
    const float* bi = (z == 0) ? bq   : (z == 1) ? bk   : bv;
    float* C        = (z == 0) ? g_Q  : (z == 1) ? g_K  : g_V;
    gemm2_body(A, B, bi, C, MROWS, DMODEL, DMODEL, (z == 0) ? 2 : 1, sm);
}

__global__ __launch_bounds__(256, 1) void gemm_out(
    const float* __restrict__ bo, float* __restrict__ out)
{
    extern __shared__ float sm[];
    gemm2_body(g_O, g_Wo, bo, out, MROWS, DMODEL, DMODEL, 0, sm);
}

// ---------------------------------------------------------------------------
// Tensor-core flash attention v2.
// grid (16,16,2), block 128 (4 warps x 32 q-rows), 2 CTAs/SM.
// Q/K/V are tf32-pre-rounded (Q also pre-scaled by 1/8) -> raw cp.async staging.
// ---------------------------------------------------------------------------
#define QT  128
#define KCH 64
#define QSTR 68
#define KSTR 68
#define VSTR 72
#define PSTR 68
#define ATTN_SMEM_FLOATS (QT*QSTR + KCH*KSTR + KCH*VSTR + QT*PSTR)  // 26368

__global__ __launch_bounds__(128, 2) void attn_mma(float* __restrict__ O)
{
    extern __shared__ float sh[];
    float* Qs = sh;
    float* Ks = Qs + QT * QSTR;
    float* Vs = Ks + KCH * KSTR;
    float* Ps = Vs + KCH * VSTR;
    uint32_t* Qu = reinterpret_cast<uint32_t*>(Qs);
    uint32_t* Ku = reinterpret_cast<uint32_t*>(Ks);
    uint32_t* Vu = reinterpret_cast<uint32_t*>(Vs);
    uint32_t* Pu = reinterpret_cast<uint32_t*>(Ps);

    const int t    = threadIdx.x;
    const int wid  = t >> 5;
    const int lane = t & 31;
    const int lq   = lane >> 2;
    const int lr4  = lane & 3;

    const int qbase = blockIdx.x * QT;
    const int h     = blockIdx.y;
    const int b     = blockIdx.z;
    const int hbase = h * DK;

    // Q staging: thread t -> row t (64 floats = 16 cp.async)
    {
        const float* src = g_Q + ((size_t)b * SEQ + qbase + t) * DMODEL + hbase;
        const uint32_t dst = smem_u32(Qu) + t * QSTR * 4;
#pragma unroll
        for (int i = 0; i < 16; i++) cp16(dst + i * 16, src + i * 4);
        CP_COMMIT();
    }

    const int qr0 = wid * 32;

    float m[2][2], l[2][2];
#pragma unroll
    for (int mt = 0; mt < 2; mt++) { m[mt][0] = m[mt][1] = -1e30f; l[mt][0] = l[mt][1] = 0.f; }
    float oacc[2][8][4];
#pragma unroll
    for (int mt = 0; mt < 2; mt++)
#pragma unroll
        for (int j = 0; j < 8; j++)
#pragma unroll
            for (int i = 0; i < 4; i++) oacc[mt][j][i] = 0.f;

    // KV staging map: row t>>1, col half (t&1)*32
    const int klr = t >> 1;
    const int klc = (t & 1) * 32;
    const uint32_t kdst = smem_u32(Ku) + (klr * KSTR + klc) * 4;
    const uint32_t vdst = smem_u32(Vu) + (klr * VSTR + klc) * 4;

    for (int j0 = 0; j0 < SEQ; j0 += KCH) {
        {
            const size_t g = ((size_t)b * SEQ + j0 + klr) * DMODEL + hbase + klc;
            const float* ksrc = g_K + g;
            const float* vsrc = g_V + g;
#pragma unroll
            for (int i = 0; i < 8; i++) { cp16(kdst + i * 16, ksrc + i * 4); }
#pragma unroll
            for (int i = 0; i < 8; i++) { cp16(vdst + i * 16, vsrc + i * 4); }
            CP_COMMIT();
        }
        CP_WAIT(0);
        __syncthreads();

        // S = Q K^T : per warp 32 rows x 64 kv
        float s[2][8][4];
#pragma unroll
        for (int mt = 0; mt < 2; mt++)
#pragma unroll
            for (int j = 0; j < 8; j++)
#pragma unroll
                for (int i = 0; i < 4; i++) s[mt][j][i] = 0.f;

#pragma unroll
        for (int ks = 0; ks < 8; ks++) {
            const int k0 = ks * 8;
            uint32_t af[2][4];
#pragma unroll
            for (int mt = 0; mt < 2; mt++) {
                const int r = qr0 + mt * 16;
                af[mt][0] = Qu[(r + lq) * QSTR + k0 + lr4];
                af[mt][1] = Qu[(r + 8 + lq) * QSTR + k0 + lr4];
                af[mt][2] = Qu[(r + lq) * QSTR + k0 + 4 + lr4];
                af[mt][3] = Qu[(r + 8 + lq) * QSTR + k0 + 4 + lr4];
            }
#pragma unroll
            for (int j = 0; j < 8; j++) {
                const uint32_t bf0 = Ku[(j * 8 + lq) * KSTR + k0 + lr4];
                const uint32_t bf1 = Ku[(j * 8 + lq) * KSTR + k0 + 4 + lr4];
#pragma unroll
                for (int mt = 0; mt < 2; mt++)
                    MMA_TF32(s[mt][j], af[mt][0], af[mt][1], af[mt][2], af[mt][3], bf0, bf1);
            }
        }

        // online softmax per m-tile
#pragma unroll
        for (int mt = 0; mt < 2; mt++) {
            float mx0 = -1e30f, mx1 = -1e30f;
#pragma unroll
            for (int j = 0; j < 8; j++) {
                mx0 = fmaxf(mx0, fmaxf(s[mt][j][0], s[mt][j][1]));
                mx1 = fmaxf(mx1, fmaxf(s[mt][j][2], s[mt][j][3]));
            }
            mx0 = fmaxf(mx0, __shfl_xor_sync(0xffffffffu, mx0, 1));
            mx0 = fmaxf(mx0, __shfl_xor_sync(0xffffffffu, mx0, 2));
            mx1 = fmaxf(mx1, __shfl_xor_sync(0xffffffffu, mx1, 1));
            mx1 = fmaxf(mx1, __shfl_xor_sync(0xffffffffu, mx1, 2));

            const float m0n = fmaxf(m[mt][0], mx0);
            const float m1n = fmaxf(m[mt][1], mx1);
            const float a0 = __expf(m[mt][0] - m0n);
            const float a1 = __expf(m[mt][1] - m1n);
            m[mt][0] = m0n; m[mt][1] = m1n;

            const int r = qr0 + mt * 16 + lq;
            float rs0 = 0.f, rs1 = 0.f;
#pragma unroll
            for (int j = 0; j < 8; j++) {
                float p0 = __expf(s[mt][j][0] - m0n);
                float p1 = __expf(s[mt][j][1] - m0n);
                float p2 = __expf(s[mt][j][2] - m1n);
                float p3 = __expf(s[mt][j][3] - m1n);
                rs0 += p0 + p1;
                rs1 += p2 + p3;
                const int cb = j * 8 + 2 * lr4;
                Pu[r * PSTR + cb]           = tf32_rn(p0);
                Pu[r * PSTR + cb + 1]       = tf32_rn(p1);
                Pu[(r + 8) * PSTR + cb]     = tf32_rn(p2);
                Pu[(r + 8) * PSTR + cb + 1] = tf32_rn(p3);
            }
            rs0 += __shfl_xor_sync(0xffffffffu, rs0, 1);
            rs0 += __shfl_xor_sync(0xffffffffu, rs0, 2);
            rs1 += __shfl_xor_sync(0xffffffffu, rs1, 1);
            rs1 += __shfl_xor_sync(0xffffffffu, rs1, 2);
            l[mt][0] = l[mt][0] * a0 + rs0;
            l[mt][1] = l[mt][1] * a1 + rs1;
#pragma unroll
            for (int j = 0; j < 8; j++) {
                oacc[mt][j][0] *= a0; oacc[mt][j][1] *= a0;
                oacc[mt][j][2] *= a1; oacc[mt][j][3] *= a1;
            }
        }
        __syncwarp();

        // O += P V
#pragma unroll
        for (int ks = 0; ks < 8; ks++) {
            const int k0 = ks * 8;
            uint32_t paf[2][4];
#pragma unroll
            for (int mt = 0; mt < 2; mt++) {
                const int r = qr0 + mt * 16;
                paf[mt][0] = Pu[(r + lq) * PSTR + k0 + lr4];
                paf[mt][1] = Pu[(r + 8 + lq) * PSTR + k0 + lr4];
                paf[mt][2] = Pu[(r + lq) * PSTR + k0 + 4 + lr4];
                paf[mt][3] = Pu[(r + 8 + lq) * PSTR + k0 + 4 + lr4];
            }
#pragma unroll
            for (int j = 0; j < 8; j++) {
                const uint32_t bf0 = Vu[(k0 + lr4) * VSTR + j * 8 + lq];
                const uint32_t bf1 = Vu[(k0 + 4 + lr4) * VSTR + j * 8 + lq];
#pragma unroll
                for (int mt = 0; mt < 2; mt++)
                    MMA_TF32(oacc[mt][j], paf[mt][0], paf[mt][1], paf[mt][2], paf[mt][3], bf0, bf1);
            }
        }
        __syncthreads();
    }

    // finalize: write tf32-rounded (feeds O-projection cp.async path)
#pragma unroll
    for (int mt = 0; mt < 2; mt++) {
        const float inv0 = 1.f / l[mt][0];
        const float inv1 = 1.f / l[mt][1];
        const size_t row0 = (size_t)b * SEQ + qbase + qr0 + mt * 16 + lq;
#pragma unroll
        for (int j = 0; j < 8; j++) {
            const int col = hbase + j * 8 + 2 * lr4;
            float2 v0 = make_float2(tf32f(oacc[mt][j][0] * inv0), tf32f(oacc[mt][j][1] * inv0));
            float2 v1 = make_float2(tf32f(oacc[mt][j][2] * inv1), tf32f(oacc[mt][j][3] * inv1));
            *reinterpret_cast<float2*>(&O[row0 * DMODEL + col]) = v0;
            *reinterpret_cast<float2*>(&O[(row0 + 8) * DMODEL + col]) = v1;
        }
    }
}

// ---------------------------------------------------------------------------
// launch
// ---------------------------------------------------------------------------
extern "C" void kernel_launch(void* const* d_in, const int* in_sizes, int n_in,
                              void* d_out, int out_size)
{
    const float* q   = (const float*)d_in[0];
    const float* k   = (const float*)d_in[1];
    const float* v   = (const float*)d_in[2];
    const float* W_q = (const float*)d_in[3];
    const float* b_q = (const float*)d_in[4];
    const float* W_k = (const float*)d_in[5];
    const float* b_k = (const float*)d_in[6];
    const float* W_v = (const float*)d_in[7];
    const float* b_v = (const float*)d_in[8];
    const float* W_o = (const float*)d_in[9];
    const float* b_o = (const float*)d_in[10];
    float* out = (float*)d_out;

    float* Op;
    cudaGetSymbolAddress((void**)&Op, g_O);

    // 1. pre-round inputs + weights
    prepass<<<dim3(1024, 7), 256>>>(q, k, v, W_q, W_k, W_v, W_o);

    // 2. fused Q/K/V projections
    cudaFuncSetAttribute(gemm_qkv, cudaFuncAttributeMaxDynamicSharedMemorySize, GEMM_SMEM);
    cudaFuncSetAttribute(gemm_out, cudaFuncAttributeMaxDynamicSharedMemorySize, GEMM_SMEM);
    dim3 qkvgrid(DMODEL / GBN, MROWS / GBM, 3);   // (4, 32, 3)
    gemm_qkv<<<qkvgrid, 256, GEMM_SMEM>>>(b_q, b_k, b_v);

    // 3. attention
    const size_t ashm = ATTN_SMEM_FLOATS * sizeof(float);  // 105472
    cudaFuncSetAttribute(attn_mma, cudaFuncAttributeMaxDynamicSharedMemorySize, (int)ashm);
    dim3 agrid(SEQ / QT, NHEADS, BATCH);   // (16, 16, 2)
    attn_mma<<<agrid, dim3(128), ashm>>>(Op);

    // 4. output projection
    dim3 ogrid(DMODEL / GBN, MROWS / GBM);  // (4, 32)
    gemm_out<<<ogrid, 256, GEMM_SMEM>>>(b_o, out);
    (void)in_sizes; (void)n_in; (void)out_size;
}

// round 7
// speedup vs baseline: 7.2302x; 2.1996x over previous
#include <cuda_runtime.h>
#include <cuda_fp16.h>
#include <cstdint>
#include <math.h>

#define BATCH 2
#define SEQ   2048
#define DMODEL 1024
#define NHEADS 16
#define DK    64
#define MROWS (BATCH*SEQ)   // 4096

// ---------------------------------------------------------------------------
// Scratch (fp16 operands + intermediates)
// ---------------------------------------------------------------------------
__device__ __align__(128) __half g_Qh[MROWS * DMODEL];
__device__ __align__(128) __half g_Kh[MROWS * DMODEL];
__device__ __align__(128) __half g_Vh[MROWS * DMODEL];
__device__ __align__(128) __half g_Oh[MROWS * DMODEL];
__device__ __align__(128) __half g_Xq[MROWS * DMODEL];
__device__ __align__(128) __half g_Xk[MROWS * DMODEL];
__device__ __align__(128) __half g_Xv[MROWS * DMODEL];
__device__ __align__(128) __half g_Wq[DMODEL * DMODEL];
__device__ __align__(128) __half g_Wk[DMODEL * DMODEL];
__device__ __align__(128) __half g_Wv[DMODEL * DMODEL];
__device__ __align__(128) __half g_Wo[DMODEL * DMODEL];

__device__ __forceinline__ uint32_t smem_u32(const void* p) {
    uint32_t a;
    asm("{ .reg .u64 t; cvta.to.shared.u64 t, %1; cvt.u32.u64 %0, t; }" : "=r"(a) : "l"(p));
    return a;
}
__device__ __forceinline__ void cp16(uint32_t dst, const void* src) {
    asm volatile("cp.async.cg.shared.global [%0], [%1], 16;" :: "r"(dst), "l"(src));
}
#define CP_COMMIT() asm volatile("cp.async.commit_group;" ::: "memory")
#define CP_WAIT(n)  asm volatile("cp.async.wait_group %0;" :: "n"(n) : "memory")

__device__ __forceinline__ void ldsm4(uint32_t* r, uint32_t a) {
    asm volatile("ldmatrix.sync.aligned.m8n8.x4.shared.b16 {%0,%1,%2,%3}, [%4];"
        : "=r"(r[0]), "=r"(r[1]), "=r"(r[2]), "=r"(r[3]) : "r"(a));
}
__device__ __forceinline__ void ldsm4t(uint32_t* r, uint32_t a) {
    asm volatile("ldmatrix.sync.aligned.m8n8.x4.trans.shared.b16 {%0,%1,%2,%3}, [%4];"
        : "=r"(r[0]), "=r"(r[1]), "=r"(r[2]), "=r"(r[3]) : "r"(a));
}
#define MMA_F16(d, a, b0, b1) \
    asm volatile( \
        "mma.sync.aligned.m16n8k16.row.col.f32.f16.f16.f32 " \
        "{%0,%1,%2,%3}, {%4,%5,%6,%7}, {%8,%9}, {%0,%1,%2,%3};" \
        : "+f"((d)[0]), "+f"((d)[1]), "+f"((d)[2]), "+f"((d)[3]) \
        : "r"((a)[0]), "r"((a)[1]), "r"((a)[2]), "r"((a)[3]), "r"(b0), "r"(b1))

// ---------------------------------------------------------------------------
// Pre-pass: fp32 -> fp16 (rn) into scratch.
// ---------------------------------------------------------------------------
__global__ __launch_bounds__(256) void prepass(
    const float* __restrict__ q, const float* __restrict__ k, const float* __restrict__ v,
    const float* __restrict__ Wq, const float* __restrict__ Wk,
    const float* __restrict__ Wv, const float* __restrict__ Wo)
{
    const float* src; __half* dst; int n4;
    switch (blockIdx.y) {
        case 0: src = q;  dst = g_Xq; n4 = MROWS * DMODEL / 4; break;
        case 1: src = k;  dst = g_Xk; n4 = MROWS * DMODEL / 4; break;
        case 2: src = v;  dst = g_Xv; n4 = MROWS * DMODEL / 4; break;
        case 3: src = Wq; dst = g_Wq; n4 = DMODEL * DMODEL / 4; break;
        case 4: src = Wk; dst = g_Wk; n4 = DMODEL * DMODEL / 4; break;
        case 5: src = Wv; dst = g_Wv; n4 = DMODEL * DMODEL / 4; break;
        default: src = Wo; dst = g_Wo; n4 = DMODEL * DMODEL / 4; break;
    }
    __half2* d2 = reinterpret_cast<__half2*>(dst);
    for (int i = blockIdx.x * blockDim.x + threadIdx.x; i < n4; i += gridDim.x * blockDim.x) {
        float4 t = reinterpret_cast<const float4*>(src)[i];
        d2[2 * i]     = __floats2half2_rn(t.x, t.y);
        d2[2 * i + 1] = __floats2half2_rn(t.z, t.w);
    }
}

// ---------------------------------------------------------------------------
// FP16 mma GEMM (NT): C[m,n] = sum_k A[m,k]*B[n,k] + bias[n]
// CTA 128x128, 8 warps of 64x32, K-chunk 32, 3-stage cp.async, ldmatrix.
// mode: 0 = fp32 out, 1 = fp16 out, 2 = fp16 out * 0.125
// ---------------------------------------------------------------------------
#define GBM 128
#define GBN 128
#define GBK 32
#define GSTR 40                       // halves/row (32 data + 8 pad) = 80B
#define GTILE_H (128 * GSTR)          // 5120 halves per tile
#define GSTG 3
#define GEMM_SMEM (GSTG * 2 * GTILE_H * 2)  // 61440 B

__device__ __forceinline__ void gemm_f16_body(
    const __half* __restrict__ A, const __half* __restrict__ B,
    const float* __restrict__ bias, float* __restrict__ Cf, __half* __restrict__ Ch,
    int mode)
{
    extern __shared__ __half smh[];
    __half* As = smh;
    __half* Bs = smh + GSTG * GTILE_H;

    const int t    = threadIdx.x;
    const int wid  = t >> 5;
    const int lane = t & 31;
    const int l7   = lane & 7;
    const int l8   = (lane >> 3) & 1;
    const int l16  = lane >> 4;
    const int lq   = lane >> 2;
    const int lr4  = lane & 3;
    const int mbase = blockIdx.y * GBM;
    const int nbase = blockIdx.x * GBN;

    // cp.async map: thread -> row t>>1, 16-half segment (t&1)
    const int srow = t >> 1, sseg = (t & 1) * 16;
    const __half* Ap = A + (size_t)(mbase + srow) * DMODEL + sseg;
    const __half* Bp = B + (size_t)(nbase + srow) * DMODEL + sseg;
    const uint32_t a_s = smem_u32(As) + (srow * GSTR + sseg) * 2;
    const uint32_t b_s = smem_u32(Bs) + (srow * GSTR + sseg) * 2;
    const uint32_t stb = GTILE_H * 2;

#define GI(c, s) { const __half* ap_ = Ap + (c) * GBK; \
        cp16(a_s + (s) * stb, ap_); cp16(a_s + (s) * stb + 16, ap_ + 8); \
        const __half* bp_ = Bp + (c) * GBK; \
        cp16(b_s + (s) * stb, bp_); cp16(b_s + (s) * stb + 16, bp_ + 8); }

    GI(0, 0); CP_COMMIT();
    GI(1, 1); CP_COMMIT();

    const int rm = (wid & 1) * 64;
    const int cn = (wid >> 1) * 32;
    const uint32_t laneA = ((l7 + 8 * l8) * GSTR + 8 * l16) * 2;
    const uint32_t laneB = ((l7 + 8 * l16) * GSTR + 8 * l8) * 2;

    float acc[4][4][4];
#pragma unroll
    for (int mt = 0; mt < 4; mt++)
#pragma unroll
        for (int nt = 0; nt < 4; nt++)
#pragma unroll
            for (int i = 0; i < 4; i++) acc[mt][nt][i] = 0.f;

    const int NCH = DMODEL / GBK;   // 32

    for (int c = 0; c < NCH; c++) {
        CP_WAIT(1);
        __syncthreads();
        const uint32_t sa = smem_u32(As) + (c % GSTG) * stb;
        const uint32_t sb = smem_u32(Bs) + (c % GSTG) * stb;
#pragma unroll
        for (int ks = 0; ks < 2; ks++) {
            const int k0 = ks * 16;
            uint32_t af[4][4], bf[2][4];
#pragma unroll
            for (int mt = 0; mt < 4; mt++)
                ldsm4(af[mt], sa + ((rm + mt * 16) * GSTR + k0) * 2 + laneA);
#pragma unroll
            for (int p = 0; p < 2; p++)
                ldsm4(bf[p], sb + ((cn + p * 16) * GSTR + k0) * 2 + laneB);
#pragma unroll
            for (int mt = 0; mt < 4; mt++)
#pragma unroll
                for (int nt = 0; nt < 4; nt++)
                    MMA_F16(acc[mt][nt], af[mt], bf[nt >> 1][(nt & 1) * 2],
                            bf[nt >> 1][(nt & 1) * 2 + 1]);
        }
        if (c + 2 < NCH) { GI(c + 2, (c + 2) % GSTG); }
        CP_COMMIT();
    }
#undef GI

#pragma unroll
    for (int mt = 0; mt < 4; mt++) {
        const int r0 = mbase + rm + mt * 16 + lq;
#pragma unroll
        for (int nt = 0; nt < 4; nt++) {
            const int col = nbase + cn + nt * 8 + lr4 * 2;
            const float bz0 = bias[col], bz1 = bias[col + 1];
            float v00 = acc[mt][nt][0] + bz0, v01 = acc[mt][nt][1] + bz1;
            float v10 = acc[mt][nt][2] + bz0, v11 = acc[mt][nt][3] + bz1;
            if (mode == 0) {
                *reinterpret_cast<float2*>(&Cf[(size_t)r0 * DMODEL + col]) = make_float2(v00, v01);
                *reinterpret_cast<float2*>(&Cf[(size_t)(r0 + 8) * DMODEL + col]) = make_float2(v10, v11);
            } else {
                if (mode == 2) { v00 *= 0.125f; v01 *= 0.125f; v10 *= 0.125f; v11 *= 0.125f; }
                *reinterpret_cast<__half2*>(&Ch[(size_t)r0 * DMODEL + col]) = __floats2half2_rn(v00, v01);
                *reinterpret_cast<__half2*>(&Ch[(size_t)(r0 + 8) * DMODEL + col]) = __floats2half2_rn(v10, v11);
            }
        }
    }
}

__global__ __launch_bounds__(256, 2) void gemm_qkv(
    const float* __restrict__ bq, const float* __restrict__ bk, const float* __restrict__ bv)
{
    const int z = blockIdx.z;
    const __half* A = (z == 0) ? g_Xq : (z == 1) ? g_Xk : g_Xv;
    const __half* B = (z == 0) ? g_Wq : (z == 1) ? g_Wk : g_Wv;
    const float* bi = (z == 0) ? bq   : (z == 1) ? bk   : bv;
    __half* C      = (z == 0) ? g_Qh : (z == 1) ? g_Kh : g_Vh;
    gemm_f16_body(A, B, bi, nullptr, C, (z == 0) ? 2 : 1);
}

__global__ __launch_bounds__(256, 2) void gemm_out(
    const float* __restrict__ bo, float* __restrict__ out)
{
    gemm_f16_body(g_Oh, g_Wo, bo, out, nullptr, 0);
}

// ---------------------------------------------------------------------------
// FP16 tensor-core flash attention, ldmatrix + double-buffered KV prefetch.
// grid (16,16,2), block 128 (4 warps x 32 q-rows), 3 CTAs/SM.
// ---------------------------------------------------------------------------
#define QT  128
#define KCH 64
#define ASTRH 72                       // halves/row (64 data + 8 pad) = 144B
#define AQ_OFF 0
#define AK_OFF (QT * ASTRH)            // 9216
#define AV_OFF (AK_OFF + 2 * KCH * ASTRH)
#define AP_OFF (AV_OFF + 2 * KCH * ASTRH)
#define ATTN_SMEM ((QT * ASTRH + 4 * KCH * ASTRH + QT * ASTRH) * 2)  // 73728 B

__global__ __launch_bounds__(128, 3) void attn_f16()
{
    extern __shared__ __half sh[];
    __half* Qs = sh + AQ_OFF;
    __half* Ks = sh + AK_OFF;
    __half* Vs = sh + AV_OFF;
    __half* Ps = sh + AP_OFF;

    const int t    = threadIdx.x;
    const int wid  = t >> 5;
    const int lane = t & 31;
    const int l7   = lane & 7;
    const int l8   = (lane >> 3) & 1;
    const int l16  = lane >> 4;
    const int lq   = lane >> 2;
    const int lr4  = lane & 3;

    const int qbase = blockIdx.x * QT;
    const int h     = blockIdx.y;
    const int b     = blockIdx.z;
    const int hbase = h * DK;

    // Q staging: thread t -> row t (64 halves = 8 cp16)
    {
        const __half* src = g_Qh + ((size_t)b * SEQ + qbase + t) * DMODEL + hbase;
        const uint32_t dst = smem_u32(Qs) + t * ASTRH * 2;
#pragma unroll
        for (int i = 0; i < 8; i++) cp16(dst + i * 16, src + i * 8);
        CP_COMMIT();
    }

    // KV staging: thread -> row t>>1, 32-half segment (t&1)
    const int klr = t >> 1;
    const int klc = (t & 1) * 32;
    const uint32_t kvoff = (klr * ASTRH + klc) * 2;
    const uint32_t bufstride = KCH * ASTRH * 2;

#define ISSUE_KV(j0, buf) { \
        const size_t g_ = ((size_t)b * SEQ + (j0) + klr) * DMODEL + hbase + klc; \
        const __half* ks_ = g_Kh + g_; const __half* vs_ = g_Vh + g_; \
        const uint32_t kd_ = smem_u32(Ks) + (buf) * bufstride + kvoff; \
        const uint32_t vd_ = smem_u32(Vs) + (buf) * bufstride + kvoff; \
        cp16(kd_, ks_); cp16(kd_ + 16, ks_ + 8); cp16(kd_ + 32, ks_ + 16); cp16(kd_ + 48, ks_ + 24); \
        cp16(vd_, vs_); cp16(vd_ + 16, vs_ + 8); cp16(vd_ + 32, vs_ + 16); cp16(vd_ + 48, vs_ + 24); \
        CP_COMMIT(); }

    ISSUE_KV(0, 0);

    const int qr0 = wid * 32;
    const uint32_t laneA = ((l7 + 8 * l8) * ASTRH + 8 * l16) * 2;   // A-type & V-trans
    const uint32_t laneB = ((l7 + 8 * l16) * ASTRH + 8 * l8) * 2;   // B-type (K)
    const uint32_t qbase_s = smem_u32(Qs);
    const uint32_t pbase_s = smem_u32(Ps);

    float m[2][2], l[2][2];
#pragma unroll
    for (int mt = 0; mt < 2; mt++) { m[mt][0] = m[mt][1] = -1e30f; l[mt][0] = l[mt][1] = 0.f; }
    float oacc[2][8][4];
#pragma unroll
    for (int mt = 0; mt < 2; mt++)
#pragma unroll
        for (int j = 0; j < 8; j++)
#pragma unroll
            for (int i = 0; i < 4; i++) oacc[mt][j][i] = 0.f;

    const int NIT = SEQ / KCH;   // 32

    for (int it = 0; it < NIT; it++) {
        const int buf = it & 1;
        CP_WAIT(0);
        __syncthreads();
        if (it + 1 < NIT) ISSUE_KV((it + 1) * KCH, buf ^ 1);

        const uint32_t sk = smem_u32(Ks) + buf * bufstride;
        const uint32_t sv = smem_u32(Vs) + buf * bufstride;

        // S = Q K^T
        float s[2][8][4];
#pragma unroll
        for (int mt = 0; mt < 2; mt++)
#pragma unroll
            for (int j = 0; j < 8; j++)
#pragma unroll
                for (int i = 0; i < 4; i++) s[mt][j][i] = 0.f;

#pragma unroll
        for (int ks = 0; ks < 4; ks++) {
            const int k0 = ks * 16;
            uint32_t af[2][4];
#pragma unroll
            for (int mt = 0; mt < 2; mt++)
                ldsm4(af[mt], qbase_s + ((qr0 + mt * 16) * ASTRH + k0) * 2 + laneA);
#pragma unroll
            for (int jp = 0; jp < 4; jp++) {
                uint32_t bf[4];
                ldsm4(bf, sk + ((jp * 16) * ASTRH + k0) * 2 + laneB);
#pragma unroll
                for (int mt = 0; mt < 2; mt++) {
                    MMA_F16(s[mt][2 * jp],     af[mt], bf[0], bf[1]);
                    MMA_F16(s[mt][2 * jp + 1], af[mt], bf[2], bf[3]);
                }
            }
        }

        // online softmax
#pragma unroll
        for (int mt = 0; mt < 2; mt++) {
            float mx0 = -1e30f, mx1 = -1e30f;
#pragma unroll
            for (int j = 0; j < 8; j++) {
                mx0 = fmaxf(mx0, fmaxf(s[mt][j][0], s[mt][j][1]));
                mx1 = fmaxf(mx1, fmaxf(s[mt][j][2], s[mt][j][3]));
            }
            mx0 = fmaxf(mx0, __shfl_xor_sync(0xffffffffu, mx0, 1));
            mx0 = fmaxf(mx0, __shfl_xor_sync(0xffffffffu, mx0, 2));
            mx1 = fmaxf(mx1, __shfl_xor_sync(0xffffffffu, mx1, 1));
            mx1 = fmaxf(mx1, __shfl_xor_sync(0xffffffffu, mx1, 2));

            const float m0n = fmaxf(m[mt][0], mx0);
            const float m1n = fmaxf(m[mt][1], mx1);
            const float a0 = __expf(m[mt][0] - m0n);
            const float a1 = __expf(m[mt][1] - m1n);
            m[mt][0] = m0n; m[mt][1] = m1n;

            const int r = qr0 + mt * 16 + lq;
            float rs0 = 0.f, rs1 = 0.f;
#pragma unroll
            for (int j = 0; j < 8; j++) {
                float p0 = __expf(s[mt][j][0] - m0n);
                float p1 = __expf(s[mt][j][1] - m0n);
                float p2 = __expf(s[mt][j][2] - m1n);
                float p3 = __expf(s[mt][j][3] - m1n);
                rs0 += p0 + p1;
                rs1 += p2 + p3;
                const int cb = j * 8 + 2 * lr4;
                *reinterpret_cast<__half2*>(&Ps[r * ASTRH + cb])       = __floats2half2_rn(p0, p1);
                *reinterpret_cast<__half2*>(&Ps[(r + 8) * ASTRH + cb]) = __floats2half2_rn(p2, p3);
            }
            rs0 += __shfl_xor_sync(0xffffffffu, rs0, 1);
            rs0 += __shfl_xor_sync(0xffffffffu, rs0, 2);
            rs1 += __shfl_xor_sync(0xffffffffu, rs1, 1);
            rs1 += __shfl_xor_sync(0xffffffffu, rs1, 2);
            l[mt][0] = l[mt][0] * a0 + rs0;
            l[mt][1] = l[mt][1] * a1 + rs1;
#pragma unroll
            for (int j = 0; j < 8; j++) {
                oacc[mt][j][0] *= a0; oacc[mt][j][1] *= a0;
                oacc[mt][j][2] *= a1; oacc[mt][j][3] *= a1;
            }
        }
        __syncwarp();

        // O += P V  (V via ldmatrix.trans)
#pragma unroll
        for (int ks = 0; ks < 4; ks++) {
            const int k0 = ks * 16;
            uint32_t paf[2][4];
#pragma unroll
            for (int mt = 0; mt < 2; mt++)
                ldsm4(paf[mt], pbase_s + ((qr0 + mt * 16) * ASTRH + k0) * 2 + laneA);
#pragma unroll
            for (int jp = 0; jp < 4; jp++) {
                uint32_t bf[4];
                ldsm4t(bf, sv + (k0 * ASTRH + jp * 16) * 2 + laneA);
#pragma unroll
                for (int mt = 0; mt < 2; mt++) {
                    MMA_F16(oacc[mt][2 * jp],     paf[mt], bf[0], bf[1]);
                    MMA_F16(oacc[mt][2 * jp + 1], paf[mt], bf[2], bf[3]);
                }
            }
        }
        __syncthreads();
    }
#undef ISSUE_KV

    // finalize -> fp16 O
#pragma unroll
    for (int mt = 0; mt < 2; mt++) {
        const float inv0 = 1.f / l[mt][0];
        const float inv1 = 1.f / l[mt][1];
        const size_t row0 = (size_t)b * SEQ + qbase + qr0 + mt * 16 + lq;
#pragma unroll
        for (int j = 0; j < 8; j++) {
            const int col = hbase + j * 8 + 2 * lr4;
            *reinterpret_cast<__half2*>(&g_Oh[row0 * DMODEL + col]) =
                __floats2half2_rn(oacc[mt][j][0] * inv0, oacc[mt][j][1] * inv0);
            *reinterpret_cast<__half2*>(&g_Oh[(row0 + 8) * DMODEL + col]) =
                __floats2half2_rn(oacc[mt][j][2] * inv1, oacc[mt][j][3] * inv1);
        }
    }
}

// ---------------------------------------------------------------------------
// launch
// ---------------------------------------------------------------------------
extern "C" void kernel_launch(void* const* d_in, const int* in_sizes, int n_in,
                              void* d_out, int out_size)
{
    const float* q   = (const float*)d_in[0];
    const float* k   = (const float*)d_in[1];
    const float* v   = (const float*)d_in[2];
    const float* W_q = (const float*)d_in[3];
    const float* b_q = (const float*)d_in[4];
    const float* W_k = (const float*)d_in[5];
    const float* b_k = (const float*)d_in[6];
    const float* W_v = (const float*)d_in[7];
    const float* b_v = (const float*)d_in[8];
    const float* W_o = (const float*)d_in[9];
    const float* b_o = (const float*)d_in[10];
    float* out = (float*)d_out;

    // 1. fp32 -> fp16 pre-pass
    prepass<<<dim3(1024, 7), 256>>>(q, k, v, W_q, W_k, W_v, W_o);

    // 2. fused Q/K/V projections
    cudaFuncSetAttribute(gemm_qkv, cudaFuncAttributeMaxDynamicSharedMemorySize, GEMM_SMEM);
    cudaFuncSetAttribute(gemm_out, cudaFuncAttributeMaxDynamicSharedMemorySize, GEMM_SMEM);
    dim3 qkvgrid(DMODEL / GBN, MROWS / GBM, 3);   // (8, 32, 3)
    gemm_qkv<<<qkvgrid, 256, GEMM_SMEM>>>(b_q, b_k, b_v);

    // 3. attention
    cudaFuncSetAttribute(attn_f16, cudaFuncAttributeMaxDynamicSharedMemorySize, ATTN_SMEM);
    dim3 agrid(SEQ / QT, NHEADS, BATCH);   // (16, 16, 2)
    attn_f16<<<agrid, dim3(128), ATTN_SMEM>>>();

    // 4. output projection
    dim3 ogrid(DMODEL / GBN, MROWS / GBM);  // (8, 32)
    gemm_out<<<ogrid, 256, GEMM_SMEM>>>(b_o, out);
    (void)in_sizes; (void)n_in; (void)out_size;
}

// round 8
// speedup vs baseline: 7.2796x; 1.0068x over previous
#include <cuda_runtime.h>
#include <cuda_fp16.h>
#include <cstdint>
#include <math.h>

#define BATCH 2
#define SEQ   2048
#define DMODEL 1024
#define NHEADS 16
#define DK    64
#define MROWS (BATCH*SEQ)   // 4096

// ---------------------------------------------------------------------------
// Scratch (fp16 operands + intermediates)
// ---------------------------------------------------------------------------
__device__ __align__(128) __half g_Qh[MROWS * DMODEL];
__device__ __align__(128) __half g_Kh[MROWS * DMODEL];
__device__ __align__(128) __half g_Vh[MROWS * DMODEL];
__device__ __align__(128) __half g_Oh[MROWS * DMODEL];
__device__ __align__(128) __half g_Xq[MROWS * DMODEL];
__device__ __align__(128) __half g_Xk[MROWS * DMODEL];
__device__ __align__(128) __half g_Xv[MROWS * DMODEL];
__device__ __align__(128) __half g_Wq[DMODEL * DMODEL];
__device__ __align__(128) __half g_Wk[DMODEL * DMODEL];
__device__ __align__(128) __half g_Wv[DMODEL * DMODEL];
__device__ __align__(128) __half g_Wo[DMODEL * DMODEL];

__device__ __forceinline__ uint32_t smem_u32(const void* p) {
    uint32_t a;
    asm("{ .reg .u64 t; cvta.to.shared.u64 t, %1; cvt.u32.u64 %0, t; }" : "=r"(a) : "l"(p));
    return a;
}
__device__ __forceinline__ void cp16(uint32_t dst, const void* src) {
    asm volatile("cp.async.cg.shared.global [%0], [%1], 16;" :: "r"(dst), "l"(src));
}
#define CP_COMMIT() asm volatile("cp.async.commit_group;" ::: "memory")
#define CP_WAIT(n)  asm volatile("cp.async.wait_group %0;" :: "n"(n) : "memory")

__device__ __forceinline__ void ldsm4(uint32_t* r, uint32_t a) {
    asm volatile("ldmatrix.sync.aligned.m8n8.x4.shared.b16 {%0,%1,%2,%3}, [%4];"
        : "=r"(r[0]), "=r"(r[1]), "=r"(r[2]), "=r"(r[3]) : "r"(a));
}
__device__ __forceinline__ void ldsm4t(uint32_t* r, uint32_t a) {
    asm volatile("ldmatrix.sync.aligned.m8n8.x4.trans.shared.b16 {%0,%1,%2,%3}, [%4];"
        : "=r"(r[0]), "=r"(r[1]), "=r"(r[2]), "=r"(r[3]) : "r"(a));
}
__device__ __forceinline__ float ex2a(float x) {
    float y; asm("ex2.approx.ftz.f32 %0, %1;" : "=f"(y) : "f"(x));
    return y;
}
#define MMA_F16(d, a, b0, b1) \
    asm volatile( \
        "mma.sync.aligned.m16n8k16.row.col.f32.f16.f16.f32 " \
        "{%0,%1,%2,%3}, {%4,%5,%6,%7}, {%8,%9}, {%0,%1,%2,%3};" \
        : "+f"((d)[0]), "+f"((d)[1]), "+f"((d)[2]), "+f"((d)[3]) \
        : "r"((a)[0]), "r"((a)[1]), "r"((a)[2]), "r"((a)[3]), "r"(b0), "r"(b1))

// Q pre-scale: 1/sqrt(64) * log2(e)  (softmax done in base 2)
#define QSCALE (0.125f * 1.44269504088896f)

// ---------------------------------------------------------------------------
// Pre-pass: fp32 -> fp16 (rn) into scratch.
// ---------------------------------------------------------------------------
__global__ __launch_bounds__(256) void prepass(
    const float* __restrict__ q, const float* __restrict__ k, const float* __restrict__ v,
    const float* __restrict__ Wq, const float* __restrict__ Wk,
    const float* __restrict__ Wv, const float* __restrict__ Wo)
{
    const float* src; __half* dst; int n4;
    switch (blockIdx.y) {
        case 0: src = q;  dst = g_Xq; n4 = MROWS * DMODEL / 4; break;
        case 1: src = k;  dst = g_Xk; n4 = MROWS * DMODEL / 4; break;
        case 2: src = v;  dst = g_Xv; n4 = MROWS * DMODEL / 4; break;
        case 3: src = Wq; dst = g_Wq; n4 = DMODEL * DMODEL / 4; break;
        case 4: src = Wk; dst = g_Wk; n4 = DMODEL * DMODEL / 4; break;
        case 5: src = Wv; dst = g_Wv; n4 = DMODEL * DMODEL / 4; break;
        default: src = Wo; dst = g_Wo; n4 = DMODEL * DMODEL / 4; break;
    }
    __half2* d2 = reinterpret_cast<__half2*>(dst);
    for (int i = blockIdx.x * blockDim.x + threadIdx.x; i < n4; i += gridDim.x * blockDim.x) {
        float4 t = reinterpret_cast<const float4*>(src)[i];
        d2[2 * i]     = __floats2half2_rn(t.x, t.y);
        d2[2 * i + 1] = __floats2half2_rn(t.z, t.w);
    }
}

// ---------------------------------------------------------------------------
// FP16 mma GEMM (NT): C[m,n] = sum_k A[m,k]*B[n,k] + bias[n]
// CTA 128x128, 8 warps of 64x32, K-chunk 32, 4-stage cp.async, ldmatrix.
// mode: 0 = fp32 out, 1 = fp16 out, 2 = fp16 out * QSCALE
// ---------------------------------------------------------------------------
#define GBM 128
#define GBN 128
#define GBK 32
#define GSTR 40                       // halves/row (32 data + 8 pad) = 80B
#define GTILE_H (128 * GSTR)          // 5120 halves per tile
#define GSTG 4
#define GEMM_SMEM (GSTG * 2 * GTILE_H * 2)  // 81920 B

__device__ __forceinline__ void gemm_f16_body(
    const __half* __restrict__ A, const __half* __restrict__ B,
    const float* __restrict__ bias, float* __restrict__ Cf, __half* __restrict__ Ch,
    int mode)
{
    extern __shared__ __half smh[];
    __half* As = smh;
    __half* Bs = smh + GSTG * GTILE_H;

    const int t    = threadIdx.x;
    const int wid  = t >> 5;
    const int lane = t & 31;
    const int l7   = lane & 7;
    const int l8   = (lane >> 3) & 1;
    const int l16  = lane >> 4;
    const int lq   = lane >> 2;
    const int lr4  = lane & 3;
    const int mbase = blockIdx.y * GBM;
    const int nbase = blockIdx.x * GBN;

    const int srow = t >> 1, sseg = (t & 1) * 16;
    const __half* Ap = A + (size_t)(mbase + srow) * DMODEL + sseg;
    const __half* Bp = B + (size_t)(nbase + srow) * DMODEL + sseg;
    const uint32_t a_s = smem_u32(As) + (srow * GSTR + sseg) * 2;
    const uint32_t b_s = smem_u32(Bs) + (srow * GSTR + sseg) * 2;
    const uint32_t stb = GTILE_H * 2;

#define GI(c, s) { const __half* ap_ = Ap + (c) * GBK; \
        cp16(a_s + (s) * stb, ap_); cp16(a_s + (s) * stb + 16, ap_ + 8); \
        const __half* bp_ = Bp + (c) * GBK; \
        cp16(b_s + (s) * stb, bp_); cp16(b_s + (s) * stb + 16, bp_ + 8); }

    GI(0, 0); CP_COMMIT();
    GI(1, 1); CP_COMMIT();
    GI(2, 2); CP_COMMIT();

    const int rm = (wid & 1) * 64;
    const int cn = (wid >> 1) * 32;
    const uint32_t laneA = ((l7 + 8 * l8) * GSTR + 8 * l16) * 2;
    const uint32_t laneB = ((l7 + 8 * l16) * GSTR + 8 * l8) * 2;

    float acc[4][4][4];
#pragma unroll
    for (int mt = 0; mt < 4; mt++)
#pragma unroll
        for (int nt = 0; nt < 4; nt++)
#pragma unroll
            for (int i = 0; i < 4; i++) acc[mt][nt][i] = 0.f;

    const int NCH = DMODEL / GBK;   // 32

    for (int c = 0; c < NCH; c++) {
        CP_WAIT(2);
        __syncthreads();
        // kick next chunk's loads first (LSU early, tensor later)
        if (c + 3 < NCH) { GI(c + 3, (c + 3) & (GSTG - 1)); }
        CP_COMMIT();

        const uint32_t sa = smem_u32(As) + (c & (GSTG - 1)) * stb;
        const uint32_t sb = smem_u32(Bs) + (c & (GSTG - 1)) * stb;
        // load both ks-steps' fragments, then run both mma bursts (max ILP)
        uint32_t af[2][4][4], bf[2][2][4];
#pragma unroll
        for (int ks = 0; ks < 2; ks++) {
            const int k0 = ks * 16;
#pragma unroll
            for (int mt = 0; mt < 4; mt++)
                ldsm4(af[ks][mt], sa + ((rm + mt * 16) * GSTR + k0) * 2 + laneA);
#pragma unroll
            for (int p = 0; p < 2; p++)
                ldsm4(bf[ks][p], sb + ((cn + p * 16) * GSTR + k0) * 2 + laneB);
        }
#pragma unroll
        for (int ks = 0; ks < 2; ks++)
#pragma unroll
            for (int mt = 0; mt < 4; mt++)
#pragma unroll
                for (int nt = 0; nt < 4; nt++)
                    MMA_F16(acc[mt][nt], af[ks][mt], bf[ks][nt >> 1][(nt & 1) * 2],
                            bf[ks][nt >> 1][(nt & 1) * 2 + 1]);
    }
#undef GI

#pragma unroll
    for (int mt = 0; mt < 4; mt++) {
        const int r0 = mbase + rm + mt * 16 + lq;
#pragma unroll
        for (int nt = 0; nt < 4; nt++) {
            const int col = nbase + cn + nt * 8 + lr4 * 2;
            const float bz0 = bias[col], bz1 = bias[col + 1];
            float v00 = acc[mt][nt][0] + bz0, v01 = acc[mt][nt][1] + bz1;
            float v10 = acc[mt][nt][2] + bz0, v11 = acc[mt][nt][3] + bz1;
            if (mode == 0) {
                *reinterpret_cast<float2*>(&Cf[(size_t)r0 * DMODEL + col]) = make_float2(v00, v01);
                *reinterpret_cast<float2*>(&Cf[(size_t)(r0 + 8) * DMODEL + col]) = make_float2(v10, v11);
            } else {
                if (mode == 2) { v00 *= QSCALE; v01 *= QSCALE; v10 *= QSCALE; v11 *= QSCALE; }
                *reinterpret_cast<__half2*>(&Ch[(size_t)r0 * DMODEL + col]) = __floats2half2_rn(v00, v01);
                *reinterpret_cast<__half2*>(&Ch[(size_t)(r0 + 8) * DMODEL + col]) = __floats2half2_rn(v10, v11);
            }
        }
    }
}

__global__ __launch_bounds__(256, 2) void gemm_qkv(
    const float* __restrict__ bq, const float* __restrict__ bk, const float* __restrict__ bv)
{
    const int z = blockIdx.z;
    const __half* A = (z == 0) ? g_Xq : (z == 1) ? g_Xk : g_Xv;
    const __half* B = (z == 0) ? g_Wq : (z == 1) ? g_Wk : g_Wv;
    const float* bi = (z == 0) ? bq   : (z == 1) ? bk   : bv;
    __half* C      = (z == 0) ? g_Qh : (z == 1) ? g_Kh : g_Vh;
    gemm_f16_body(A, B, bi, nullptr, C, (z == 0) ? 2 : 1);
}

__global__ __launch_bounds__(256, 2) void gemm_out(
    const float* __restrict__ bo, float* __restrict__ out)
{
    gemm_f16_body(g_Oh, g_Wo, bo, out, nullptr, 0);
}

// ---------------------------------------------------------------------------
// FP16 tensor-core flash attention, ldmatrix + double-buffered KV prefetch.
// grid (16,16,2), block 128 (4 warps x 32 q-rows), 3 CTAs/SM.
// Softmax in base 2 (Q pre-scaled by 0.125*log2e in projection).
// One __syncthreads per KV chunk.
// ---------------------------------------------------------------------------
#define QT  128
#define KCH 64
#define ASTRH 72                       // halves/row (64 data + 8 pad) = 144B
#define AQ_OFF 0
#define AK_OFF (QT * ASTRH)
#define AV_OFF (AK_OFF + 2 * KCH * ASTRH)
#define AP_OFF (AV_OFF + 2 * KCH * ASTRH)
#define ATTN_SMEM ((QT * ASTRH + 4 * KCH * ASTRH + QT * ASTRH) * 2)  // 73728 B

__global__ __launch_bounds__(128, 3) void attn_f16()
{
    extern __shared__ __half sh[];
    __half* Qs = sh + AQ_OFF;
    __half* Ks = sh + AK_OFF;
    __half* Vs = sh + AV_OFF;
    __half* Ps = sh + AP_OFF;

    const int t    = threadIdx.x;
    const int wid  = t >> 5;
    const int lane = t & 31;
    const int l7   = lane & 7;
    const int l8   = (lane >> 3) & 1;
    const int l16  = lane >> 4;
    const int lq   = lane >> 2;
    const int lr4  = lane & 3;

    const int qbase = blockIdx.x * QT;
    const int h     = blockIdx.y;
    const int b     = blockIdx.z;
    const int hbase = h * DK;

    // Q staging: thread t -> row t
    {
        const __half* src = g_Qh + ((size_t)b * SEQ + qbase + t) * DMODEL + hbase;
        const uint32_t dst = smem_u32(Qs) + t * ASTRH * 2;
#pragma unroll
        for (int i = 0; i < 8; i++) cp16(dst + i * 16, src + i * 8);
        CP_COMMIT();
    }

    const int klr = t >> 1;
    const int klc = (t & 1) * 32;
    const uint32_t kvoff = (klr * ASTRH + klc) * 2;
    const uint32_t bufstride = KCH * ASTRH * 2;

#define ISSUE_KV(j0, buf) { \
        const size_t g_ = ((size_t)b * SEQ + (j0) + klr) * DMODEL + hbase + klc; \
        const __half* ks_ = g_Kh + g_; const __half* vs_ = g_Vh + g_; \
        const uint32_t kd_ = smem_u32(Ks) + (buf) * bufstride + kvoff; \
        const uint32_t vd_ = smem_u32(Vs) + (buf) * bufstride + kvoff; \
        cp16(kd_, ks_); cp16(kd_ + 16, ks_ + 8); cp16(kd_ + 32, ks_ + 16); cp16(kd_ + 48, ks_ + 24); \
        cp16(vd_, vs_); cp16(vd_ + 16, vs_ + 8); cp16(vd_ + 32, vs_ + 16); cp16(vd_ + 48, vs_ + 24); \
        CP_COMMIT(); }

    ISSUE_KV(0, 0);

    const int qr0 = wid * 32;
    const uint32_t laneA = ((l7 + 8 * l8) * ASTRH + 8 * l16) * 2;   // A-type & V-trans
    const uint32_t laneB = ((l7 + 8 * l16) * ASTRH + 8 * l8) * 2;   // B-type (K)
    const uint32_t qbase_s = smem_u32(Qs);
    const uint32_t pbase_s = smem_u32(Ps);

    float m[2][2], l[2][2];
#pragma unroll
    for (int mt = 0; mt < 2; mt++) { m[mt][0] = m[mt][1] = -1e30f; l[mt][0] = l[mt][1] = 0.f; }
    float oacc[2][8][4];
#pragma unroll
    for (int mt = 0; mt < 2; mt++)
#pragma unroll
        for (int j = 0; j < 8; j++)
#pragma unroll
            for (int i = 0; i < 4; i++) oacc[mt][j][i] = 0.f;

    const int NIT = SEQ / KCH;   // 32

    for (int it = 0; it < NIT; it++) {
        const int buf = it & 1;
        CP_WAIT(0);
        __syncthreads();               // single barrier per chunk
        if (it + 1 < NIT) ISSUE_KV((it + 1) * KCH, buf ^ 1);

        const uint32_t sk = smem_u32(Ks) + buf * bufstride;
        const uint32_t sv = smem_u32(Vs) + buf * bufstride;

        // S = Q K^T
        float s[2][8][4];
#pragma unroll
        for (int mt = 0; mt < 2; mt++)
#pragma unroll
            for (int j = 0; j < 8; j++)
#pragma unroll
                for (int i = 0; i < 4; i++) s[mt][j][i] = 0.f;

#pragma unroll
        for (int ks = 0; ks < 4; ks++) {
            const int k0 = ks * 16;
            uint32_t af[2][4];
#pragma unroll
            for (int mt = 0; mt < 2; mt++)
                ldsm4(af[mt], qbase_s + ((qr0 + mt * 16) * ASTRH + k0) * 2 + laneA);
#pragma unroll
            for (int jp = 0; jp < 4; jp++) {
                uint32_t bf[4];
                ldsm4(bf, sk + ((jp * 16) * ASTRH + k0) * 2 + laneB);
#pragma unroll
                for (int mt = 0; mt < 2; mt++) {
                    MMA_F16(s[mt][2 * jp],     af[mt], bf[0], bf[1]);
                    MMA_F16(s[mt][2 * jp + 1], af[mt], bf[2], bf[3]);
                }
            }
        }

        // online softmax (base 2)
#pragma unroll
        for (int mt = 0; mt < 2; mt++) {
            float mx0 = -1e30f, mx1 = -1e30f;
#pragma unroll
            for (int j = 0; j < 8; j++) {
                mx0 = fmaxf(mx0, fmaxf(s[mt][j][0], s[mt][j][1]));
                mx1 = fmaxf(mx1, fmaxf(s[mt][j][2], s[mt][j][3]));
            }
            mx0 = fmaxf(mx0, __shfl_xor_sync(0xffffffffu, mx0, 1));
            mx0 = fmaxf(mx0, __shfl_xor_sync(0xffffffffu, mx0, 2));
            mx1 = fmaxf(mx1, __shfl_xor_sync(0xffffffffu, mx1, 1));
            mx1 = fmaxf(mx1, __shfl_xor_sync(0xffffffffu, mx1, 2));

            const float m0n = fmaxf(m[mt][0], mx0);
            const float m1n = fmaxf(m[mt][1], mx1);
            const float a0 = ex2a(m[mt][0] - m0n);
            const float a1 = ex2a(m[mt][1] - m1n);
            m[mt][0] = m0n; m[mt][1] = m1n;

            const int r = qr0 + mt * 16 + lq;
            float rs0 = 0.f, rs1 = 0.f;
#pragma unroll
            for (int j = 0; j < 8; j++) {
                float p0 = ex2a(s[mt][j][0] - m0n);
                float p1 = ex2a(s[mt][j][1] - m0n);
                float p2 = ex2a(s[mt][j][2] - m1n);
                float p3 = ex2a(s[mt][j][3] - m1n);
                rs0 += p0 + p1;
                rs1 += p2 + p3;
                const int cb = j * 8 + 2 * lr4;
                *reinterpret_cast<__half2*>(&Ps[r * ASTRH + cb])       = __floats2half2_rn(p0, p1);
                *reinterpret_cast<__half2*>(&Ps[(r + 8) * ASTRH + cb]) = __floats2half2_rn(p2, p3);
            }
            rs0 += __shfl_xor_sync(0xffffffffu, rs0, 1);
            rs0 += __shfl_xor_sync(0xffffffffu, rs0, 2);
            rs1 += __shfl_xor_sync(0xffffffffu, rs1, 1);
            rs1 += __shfl_xor_sync(0xffffffffu, rs1, 2);
            l[mt][0] = l[mt][0] * a0 + rs0;
            l[mt][1] = l[mt][1] * a1 + rs1;
#pragma unroll
            for (int j = 0; j < 8; j++) {
                oacc[mt][j][0] *= a0; oacc[mt][j][1] *= a0;
                oacc[mt][j][2] *= a1; oacc[mt][j][3] *= a1;
            }
        }
        __syncwarp();

        // O += P V  (V via ldmatrix.trans)
#pragma unroll
        for (int ks = 0; ks < 4; ks++) {
            const int k0 = ks * 16;
            uint32_t paf[2][4];
#pragma unroll
            for (int mt = 0; mt < 2; mt++)
                ldsm4(paf[mt], pbase_s + ((qr0 + mt * 16) * ASTRH + k0) * 2 + laneA);
#pragma unroll
            for (int jp = 0; jp < 4; jp++) {
                uint32_t bf[4];
                ldsm4t(bf, sv + (k0 * ASTRH + jp * 16) * 2 + laneA);
#pragma unroll
                for (int mt = 0; mt < 2; mt++) {
                    MMA_F16(oacc[mt][2 * jp],     paf[mt], bf[0], bf[1]);
                    MMA_F16(oacc[mt][2 * jp + 1], paf[mt], bf[2], bf[3]);
                }
            }
        }
        // no trailing barrier: next iteration's CP_WAIT+sync covers WAR on buf
    }
#undef ISSUE_KV

    // finalize -> fp16 O
#pragma unroll
    for (int mt = 0; mt < 2; mt++) {
        const float inv0 = 1.f / l[mt][0];
        const float inv1 = 1.f / l[mt][1];
        const size_t row0 = (size_t)b * SEQ + qbase + qr0 + mt * 16 + lq;
#pragma unroll
        for (int j = 0; j < 8; j++) {
            const int col = hbase + j * 8 + 2 * lr4;
            *reinterpret_cast<__half2*>(&g_Oh[row0 * DMODEL + col]) =
                __floats2half2_rn(oacc[mt][j][0] * inv0, oacc[mt][j][1] * inv0);
            *reinterpret_cast<__half2*>(&g_Oh[(row0 + 8) * DMODEL + col]) =
                __floats2half2_rn(oacc[mt][j][2] * inv1, oacc[mt][j][3] * inv1);
        }
    }
}

// ---------------------------------------------------------------------------
// launch
// ---------------------------------------------------------------------------
extern "C" void kernel_launch(void* const* d_in, const int* in_sizes, int n_in,
                              void* d_out, int out_size)
{
    const float* q   = (const float*)d_in[0];
    const float* k   = (const float*)d_in[1];
    const float* v   = (const float*)d_in[2];
    const float* W_q = (const float*)d_in[3];
    const float* b_q = (const float*)d_in[4];
    const float* W_k = (const float*)d_in[5];
    const float* b_k = (const float*)d_in[6];
    const float* W_v = (const float*)d_in[7];
    const float* b_v = (const float*)d_in[8];
    const float* W_o = (const float*)d_in[9];
    const float* b_o = (const float*)d_in[10];
    float* out = (float*)d_out;

    prepass<<<dim3(1024, 7), 256>>>(q, k, v, W_q, W_k, W_v, W_o);

    cudaFuncSetAttribute(gemm_qkv, cudaFuncAttributeMaxDynamicSharedMemorySize, GEMM_SMEM);
    cudaFuncSetAttribute(gemm_out, cudaFuncAttributeMaxDynamicSharedMemorySize, GEMM_SMEM);
    dim3 qkvgrid(DMODEL / GBN, MROWS / GBM, 3);   // (8, 32, 3)
    gemm_qkv<<<qkvgrid, 256, GEMM_SMEM>>>(b_q, b_k, b_v);

    cudaFuncSetAttribute(attn_f16, cudaFuncAttributeMaxDynamicSharedMemorySize, ATTN_SMEM);
    dim3 agrid(SEQ / QT, NHEADS, BATCH);   // (16, 16, 2)
    attn_f16<<<agrid, dim3(128), ATTN_SMEM>>>();

    dim3 ogrid(DMODEL / GBN, MROWS / GBM);  // (8, 32)
    gemm_out<<<ogrid, 256, GEMM_SMEM>>>(b_o, out);
    (void)in_sizes; (void)n_in; (void)out_size;
}